// round 14
// baseline (speedup 1.0000x reference)
#include <cuda_runtime.h>
#include <cuda_bf16.h>
#include <cstdint>
#include <math.h>

#define NN 2048
#define EE 16384
#define SS 256
#define DHH 128
#define H2C 256
#define DMC 256
#define G3C 768
#define SPECIAL 2040
#define NB 4096

// ---------------- device scratch ----------------
__device__ __align__(256) float d_h[NB*H2C];
__device__ __align__(256) float d_EB[16*1024];
__device__ __align__(256) float d_bias1[4*1024];
__device__ __align__(256) float d_G1[NB*1024];
__device__ __align__(256) float d_gi[NB*G3C];
__device__ __align__(256) __nv_bfloat16 d_hhi[NB*H2C];
__device__ __align__(256) __nv_bfloat16 d_hlo[NB*H2C];
__device__ __align__(256) __nv_bfloat16 d_agghi[NB*H2C];
__device__ __align__(256) __nv_bfloat16 d_agglo[NB*H2C];
__device__ __align__(256) __nv_bfloat16 d_B1t_hi[4*1024*256];
__device__ __align__(256) __nv_bfloat16 d_B1t_lo[4*1024*256];
__device__ __align__(256) __nv_bfloat16 d_B2t_hi[4*768*256];
__device__ __align__(256) __nv_bfloat16 d_B2t_lo[4*768*256];
__device__ __align__(256) __nv_bfloat16 d_W2t_hi[2*256*256];
__device__ __align__(256) __nv_bfloat16 d_W2t_lo[2*256*256];
__device__ int   d_offs[2*(NN+1)];
__device__ int   d_list[2*EE];
__device__ int   d_gl[2*EE];
__device__ float d_tA[4*NN];
__device__ float d_tB[4*8];
__device__ float d_Mx[4];
__device__ float d_pNum[4*16*DHH];
__device__ float d_pDen[4*16];
__device__ __align__(256) float d_pooled[4*SS*DHH];
__device__ __align__(256) float d_QI[4*SS*DMC];
__device__ float d_ho[2*SS*SS];

// ---------------- helpers ----------------
__device__ __forceinline__ uint32_t smem_u32(const void* p){
  uint32_t a; asm("{ .reg .u64 t; cvta.to.shared.u64 t, %1; cvt.u32.u64 %0, t; }" : "=r"(a) : "l"(p)); return a;
}
__device__ __forceinline__ void mma16816(float* c, const uint32_t* a, const uint32_t* b){
  asm volatile(
    "mma.sync.aligned.m16n8k16.row.col.f32.bf16.bf16.f32 "
    "{%0,%1,%2,%3}, {%4,%5,%6,%7}, {%8,%9}, {%0,%1,%2,%3};"
    : "+f"(c[0]), "+f"(c[1]), "+f"(c[2]), "+f"(c[3])
    : "r"(a[0]), "r"(a[1]), "r"(a[2]), "r"(a[3]), "r"(b[0]), "r"(b[1]));
}
__device__ __forceinline__ void ldmx4(uint32_t* r, uint32_t addr){
  asm volatile("ldmatrix.sync.aligned.m8n8.x4.shared.b16 {%0,%1,%2,%3}, [%4];"
    : "=r"(r[0]), "=r"(r[1]), "=r"(r[2]), "=r"(r[3]) : "r"(addr));
}

// ---------------- split-bf16 HMMA GEMM (loop GEMMs) ----------------
#define HSMEM 65536
__device__ __forceinline__ void h_load(int tid, uint32_t base,
  const __nv_bfloat16* Ahi, const __nv_bfloat16* Alo,
  const __nv_bfloat16* Bhi, const __nv_bfloat16* Blo,
  int m0, int n0, int c)
{
  const __nv_bfloat16* srcs[4] = { Ahi, Alo, Bhi, Blo };
  int rows0[4] = { m0, m0, n0, n0 };
  #pragma unroll
  for(int a=0;a<4;a++){
    const __nv_bfloat16* S = srcs[a];
    uint32_t dbase = base + a*8192u;
    int row0 = rows0[a];
    #pragma unroll
    for(int i=0;i<2;i++){
      int u = tid + i*256;
      int r = u>>2, col = u&3;
      const void* src = S + (size_t)(row0+r)*256 + c*32 + col*8;
      uint32_t dst = dbase + (uint32_t)(r*64) + (uint32_t)((col ^ ((r>>1)&3))<<4);
      asm volatile("cp.async.cg.shared.global [%0], [%1], 16;" :: "r"(dst), "l"(src));
    }
  }
  asm volatile("cp.async.commit_group;");
}

__global__ void __launch_bounds__(256,2) hmma(int Msplit,
  const __nv_bfloat16* __restrict__ Ahi, const __nv_bfloat16* __restrict__ Alo,
  const __nv_bfloat16* __restrict__ Bhi0, const __nv_bfloat16* __restrict__ Blo0,
  const __nv_bfloat16* __restrict__ Bhi1, const __nv_bfloat16* __restrict__ Blo1,
  const float* __restrict__ bias0, const float* __restrict__ bias1,
  float* __restrict__ C, int ldc)
{
  extern __shared__ char smem[];
  uint32_t sb = smem_u32(smem);
  int tid=threadIdx.x, lane=tid&31, wid=tid>>5;
  int m0=blockIdx.y*128, n0=blockIdx.x*128;
  const __nv_bfloat16* Bhi=(m0<Msplit)?Bhi0:Bhi1;
  const __nv_bfloat16* Blo=(m0<Msplit)?Blo0:Blo1;
  const float* bias=(m0<Msplit)?bias0:bias1;
  int wm = wid>>2, wn = wid&3;

  float acc[4][4][4];
  #pragma unroll
  for(int i=0;i<4;i++)
    #pragma unroll
    for(int j=0;j<4;j++)
      #pragma unroll
      for(int k=0;k<4;k++) acc[i][j][k]=0.f;

  h_load(tid, sb, Ahi, Alo, Bhi, Blo, m0, n0, 0);

  for(int c=0;c<8;c++){
    uint32_t buf = sb + (uint32_t)(c&1)*32768u;
    asm volatile("cp.async.wait_group 0;");
    __syncthreads();
    if(c<7)
      h_load(tid, sb + (uint32_t)((c+1)&1)*32768u, Ahi, Alo, Bhi, Blo, m0, n0, c+1);

    uint32_t aHB=buf, aLB=buf+8192u, bHB=buf+16384u, bLB=buf+24576u;
    #pragma unroll
    for(int ks=0; ks<2; ks++){
      uint32_t bh[4][2], bl[4][2];
      {
        int rn = wn*32 + ((lane>>4)<<3) + (lane&7);
        int cB = 2*ks + ((lane>>3)&1);
        #pragma unroll
        for(int nip=0; nip<2; nip++){
          int r = rn + nip*16;
          uint32_t off = (uint32_t)(r*64) + (uint32_t)((cB ^ ((r>>1)&3))<<4);
          uint32_t t[4];
          ldmx4(t, bHB + off);
          bh[2*nip][0]=t[0]; bh[2*nip][1]=t[1]; bh[2*nip+1][0]=t[2]; bh[2*nip+1][1]=t[3];
          ldmx4(t, bLB + off);
          bl[2*nip][0]=t[0]; bl[2*nip][1]=t[1]; bl[2*nip+1][0]=t[2]; bl[2*nip+1][1]=t[3];
        }
      }
      uint32_t af[4][4];
      int rA = lane&15, cA = 2*ks + (lane>>4);
      #pragma unroll
      for(int mi=0;mi<4;mi++){
        int r = wm*64 + mi*16 + rA;
        uint32_t off = (uint32_t)(r*64) + (uint32_t)((cA ^ ((r>>1)&3))<<4);
        ldmx4(af[mi], aHB + off);
      }
      #pragma unroll
      for(int mi=0;mi<4;mi++)
        #pragma unroll
        for(int ni=0;ni<4;ni++)
          mma16816(acc[mi][ni], af[mi], bh[ni]);   // hi*hi
      #pragma unroll
      for(int mi=0;mi<4;mi++)
        #pragma unroll
        for(int ni=0;ni<4;ni++)
          mma16816(acc[mi][ni], af[mi], bl[ni]);   // hi*lo
      #pragma unroll
      for(int mi=0;mi<4;mi++){
        int r = wm*64 + mi*16 + rA;
        uint32_t off = (uint32_t)(r*64) + (uint32_t)((cA ^ ((r>>1)&3))<<4);
        ldmx4(af[mi], aLB + off);
      }
      #pragma unroll
      for(int mi=0;mi<4;mi++)
        #pragma unroll
        for(int ni=0;ni<4;ni++)
          mma16816(acc[mi][ni], af[mi], bh[ni]);   // lo*hi
    }
  }

  int gr = lane>>2, gc = (lane&3)*2;
  #pragma unroll
  for(int mi=0;mi<4;mi++){
    int r1 = m0 + wm*64 + mi*16 + gr;
    #pragma unroll
    for(int ni=0;ni<4;ni++){
      int col = n0 + wn*32 + ni*8 + gc;
      float b0 = bias[col], b1 = bias[col+1];
      float2 v0 = make_float2(acc[mi][ni][0]+b0, acc[mi][ni][1]+b1);
      float2 v1 = make_float2(acc[mi][ni][2]+b0, acc[mi][ni][3]+b1);
      *(float2*)(C + (size_t)r1*ldc + col) = v0;
      *(float2*)(C + (size_t)(r1+8)*ldc + col) = v1;
    }
  }
}

// ---------------- fused readout (96KB smem -> 2 CTAs/SM) ----------------
#define ROSMEM 98304
__global__ void __launch_bounds__(256,2) k_ro(
  const float* __restrict__ rb1, const float* __restrict__ rg1, const float* __restrict__ rbe1,
  const float* __restrict__ rb2, const float* __restrict__ rg2, const float* __restrict__ rbe2,
  const float* __restrict__ rW3, const float* __restrict__ rb3)
{
  extern __shared__ char smem[];
  uint32_t sb = smem_u32(smem);
  int h = blockIdx.y;
  int tid=threadIdx.x, lane=tid&31, wid=tid>>5;
  int wm=wid>>2, wn=wid&3;
  int row0 = blockIdx.x*64;

  const float* Q1 = d_QI + (size_t)(2*h)*65536;
  const float* I1 = d_QI + (size_t)(2*h+1)*65536;
  const float* b1 = rb1 + h*256;
  const float* g1 = rg1 + h*256;
  const float* be1 = rbe1 + h*256;
  const __nv_bfloat16* Wh = d_W2t_hi + (size_t)h*65536;
  const __nv_bfloat16* Wl = d_W2t_lo + (size_t)h*65536;

  #define RO_BLOAD(cc) do{ \
    uint32_t base_ = sb + 65536u; \
    _Pragma("unroll") \
    for(int i_=0;i_<4;i_++){ \
      int u_ = tid + i_*256; int r_=u_>>2, col_=u_&3; \
      const void* sh_ = Wh + (size_t)r_*256 + (cc)*32 + col_*8; \
      const void* sl_ = Wl + (size_t)r_*256 + (cc)*32 + col_*8; \
      uint32_t d_ = base_ + (uint32_t)(r_*64) + (uint32_t)((col_ ^ ((r_>>1)&3))<<4); \
      asm volatile("cp.async.cg.shared.global [%0], [%1], 16;" :: "r"(d_), "l"(sh_)); \
      asm volatile("cp.async.cg.shared.global [%0], [%1], 16;" :: "r"(d_+16384u), "l"(sl_)); \
    } \
    asm volatile("cp.async.commit_group;"); \
  }while(0)

  RO_BLOAD(0);

  {
    int rl = tid>>2, cg = tid&3;
    int grow = row0 + rl;
    int a = grow>>8, b = grow&255;
    const float* qrow = Q1 + (size_t)b*256 + cg*64;
    const float* irow = I1 + (size_t)a*256 + cg*64;
    const float* brow = b1 + cg*64;
    float s1=0.f, s2=0.f;
    #pragma unroll 8
    for(int i=0;i<64;i++){
      float z = qrow[i]+irow[i]+brow[i];
      s1+=z; s2+=z*z;
    }
    s1 += __shfl_xor_sync(0xffffffffu,s1,1); s2 += __shfl_xor_sync(0xffffffffu,s2,1);
    s1 += __shfl_xor_sync(0xffffffffu,s1,2); s2 += __shfl_xor_sync(0xffffffffu,s2,2);
    float mean = s1*(1.f/256.f);
    float rstd = rsqrtf(s2*(1.f/256.f)-mean*mean+1e-5f);
    const float* g1c = g1 + cg*64;
    const float* be1c = be1 + cg*64;
    #pragma unroll
    for(int g=0; g<8; g++){
      uint32_t hi4[4], lo4[4];
      #pragma unroll
      for(int ii=0; ii<4; ii++){
        int j = g*8 + 2*ii;
        float z0 = qrow[j]+irow[j]+brow[j];
        float z1 = qrow[j+1]+irow[j+1]+brow[j+1];
        float v0 = fmaxf((z0-mean)*rstd*g1c[j]+be1c[j], 0.f);
        float v1 = fmaxf((z1-mean)*rstd*g1c[j+1]+be1c[j+1], 0.f);
        __nv_bfloat16 h0=__float2bfloat16(v0), h1=__float2bfloat16(v1);
        __nv_bfloat16 l0=__float2bfloat16(v0-__bfloat162float(h0));
        __nv_bfloat16 l1=__float2bfloat16(v1-__bfloat162float(h1));
        hi4[ii] = ((uint32_t)__bfloat16_as_ushort(h1)<<16) | (uint32_t)__bfloat16_as_ushort(h0);
        lo4[ii] = ((uint32_t)__bfloat16_as_ushort(l1)<<16) | (uint32_t)__bfloat16_as_ushort(l0);
      }
      int c16 = cg*8+g;
      uint32_t off = (uint32_t)(rl*512) + (uint32_t)((c16 ^ (rl&7))<<4);
      *(uint4*)(smem + off) = make_uint4(hi4[0],hi4[1],hi4[2],hi4[3]);
      *(uint4*)(smem + 32768 + off) = make_uint4(lo4[0],lo4[1],lo4[2],lo4[3]);
    }
  }
  __syncthreads();

  float acc[2][8][4];
  #pragma unroll
  for(int i=0;i<2;i++)
    #pragma unroll
    for(int j=0;j<8;j++)
      #pragma unroll
      for(int k=0;k<4;k++) acc[i][j][k]=0.f;

  for(int c=0;c<8;c++){
    asm volatile("cp.async.wait_group 0;");
    __syncthreads();
    uint32_t bB = sb + 65536u;
    #pragma unroll
    for(int ks=0;ks<2;ks++){
      uint32_t ahi[2][4], alo[2][4];
      int rA = lane&15;
      int c16 = c*4 + ks*2 + (lane>>4);
      #pragma unroll
      for(int mi=0;mi<2;mi++){
        int row = wm*32 + mi*16 + rA;
        uint32_t off = (uint32_t)(row*512) + (uint32_t)((c16 ^ (row&7))<<4);
        ldmx4(ahi[mi], sb + off);
        ldmx4(alo[mi], sb + 32768u + off);
      }
      uint32_t bh[8][2], bl[8][2];
      int rn = wn*64 + ((lane>>4)<<3) + (lane&7);
      int cB = 2*ks + ((lane>>3)&1);
      #pragma unroll
      for(int nip=0;nip<4;nip++){
        int r = rn + nip*16;
        uint32_t off = (uint32_t)(r*64) + (uint32_t)((cB ^ ((r>>1)&3))<<4);
        uint32_t t[4];
        ldmx4(t, bB + off);
        bh[2*nip][0]=t[0]; bh[2*nip][1]=t[1]; bh[2*nip+1][0]=t[2]; bh[2*nip+1][1]=t[3];
        ldmx4(t, bB + 16384u + off);
        bl[2*nip][0]=t[0]; bl[2*nip][1]=t[1]; bl[2*nip+1][0]=t[2]; bl[2*nip+1][1]=t[3];
      }
      #pragma unroll
      for(int mi=0;mi<2;mi++)
        #pragma unroll
        for(int ni=0;ni<8;ni++)
          mma16816(acc[mi][ni], ahi[mi], bh[ni]);
      #pragma unroll
      for(int mi=0;mi<2;mi++)
        #pragma unroll
        for(int ni=0;ni<8;ni++)
          mma16816(acc[mi][ni], ahi[mi], bl[ni]);
      #pragma unroll
      for(int mi=0;mi<2;mi++)
        #pragma unroll
        for(int ni=0;ni<8;ni++)
          mma16816(acc[mi][ni], alo[mi], bh[ni]);
    }
    __syncthreads();
    if(c<7) RO_BLOAD(c+1);
  }

  const float* b2 = rb2 + h*256;
  const float* g2 = rg2 + h*256;
  const float* be2 = rbe2 + h*256;
  const float* W3 = rW3 + h*256;
  float* ps = (float*)smem;
  float* pq = ps + 256;
  float* pd = pq + 256;
  float* mn2 = pd + 256;
  float* rs2 = mn2 + 64;
  int gr=lane>>2, gc=(lane&3)*2;
  #pragma unroll
  for(int mi=0;mi<2;mi++){
    #pragma unroll
    for(int half=0;half<2;half++){
      float s=0.f,q=0.f;
      #pragma unroll
      for(int ni=0;ni<8;ni++){
        int col = wn*64 + ni*8 + gc;
        float y0 = acc[mi][ni][half*2+0] + b2[col];
        float y1 = acc[mi][ni][half*2+1] + b2[col+1];
        s += y0+y1; q += y0*y0+y1*y1;
      }
      s += __shfl_xor_sync(0xffffffffu,s,1); q += __shfl_xor_sync(0xffffffffu,q,1);
      s += __shfl_xor_sync(0xffffffffu,s,2); q += __shfl_xor_sync(0xffffffffu,q,2);
      if((lane&3)==0){
        int rl2 = wm*32+mi*16+half*8+gr;
        ps[rl2*4+wn]=s; pq[rl2*4+wn]=q;
      }
    }
  }
  __syncthreads();
  if(tid<64){
    float s=ps[tid*4]+ps[tid*4+1]+ps[tid*4+2]+ps[tid*4+3];
    float q=pq[tid*4]+pq[tid*4+1]+pq[tid*4+2]+pq[tid*4+3];
    float m=s*(1.f/256.f);
    mn2[tid]=m; rs2[tid]=rsqrtf(q*(1.f/256.f)-m*m+1e-5f);
  }
  __syncthreads();
  #pragma unroll
  for(int mi=0;mi<2;mi++){
    #pragma unroll
    for(int half=0;half<2;half++){
      int rl2 = wm*32+mi*16+half*8+gr;
      float m=mn2[rl2], rs=rs2[rl2];
      float dsum=0.f;
      #pragma unroll
      for(int ni=0;ni<8;ni++){
        int col = wn*64 + ni*8 + gc;
        float y0 = acc[mi][ni][half*2+0] + b2[col];
        float y1 = acc[mi][ni][half*2+1] + b2[col+1];
        float u0 = fmaxf((y0-m)*rs*g2[col]+be2[col], 0.f);
        float u1 = fmaxf((y1-m)*rs*g2[col+1]+be2[col+1], 0.f);
        dsum += u0*W3[col] + u1*W3[col+1];
      }
      dsum += __shfl_xor_sync(0xffffffffu,dsum,1);
      dsum += __shfl_xor_sync(0xffffffffu,dsum,2);
      if((lane&3)==0) pd[rl2*4+wn]=dsum;
    }
  }
  __syncthreads();
  if(tid<64)
    d_ho[(size_t)h*65536 + row0 + tid] =
      pd[tid*4]+pd[tid*4+1]+pd[tid*4+2]+pd[tid*4+3] + rb3[h];
}

// ---------------- block reductions ----------------
template<int NT>
__device__ __forceinline__ float blkSum(float v){
  __shared__ float sh[NT/32];
  __shared__ float tot;
  int lane=threadIdx.x&31, w=threadIdx.x>>5;
  #pragma unroll
  for(int o=16;o>0;o>>=1) v+=__shfl_down_sync(0xffffffffu,v,o);
  if(lane==0) sh[w]=v;
  __syncthreads();
  if(w==0){
    float x=(lane<NT/32)? sh[lane] : 0.f;
    #pragma unroll
    for(int o=(NT/32)/2;o>0;o>>=1) x+=__shfl_down_sync(0xffffffffu,x,o);
    if(lane==0) tot=x;
  }
  __syncthreads();
  return tot;
}
template<int NT>
__device__ __forceinline__ float blkMax(float v){
  __shared__ float sh[NT/32];
  __shared__ float tot;
  int lane=threadIdx.x&31, w=threadIdx.x>>5;
  #pragma unroll
  for(int o=16;o>0;o>>=1) v=fmaxf(v,__shfl_down_sync(0xffffffffu,v,o));
  if(lane==0) sh[w]=v;
  __syncthreads();
  if(w==0){
    float x=(lane<NT/32)? sh[lane] : -1e30f;
    #pragma unroll
    for(int o=(NT/32)/2;o>0;o>>=1) x=fmaxf(x,__shfl_down_sync(0xffffffffu,x,o));
    if(lane==0) tot=x;
  }
  __syncthreads();
  return tot;
}

// ---------------- prep: init GEMM + weight pack + CSR in ONE kernel ----------------
__device__ __forceinline__ void sgemm64(
  const float* __restrict__ A,int lda,const float* __restrict__ B,int ldb,
  const float* __restrict__ bias, float* __restrict__ C,int ldc,
  __nv_bfloat16* Chi, __nv_bfloat16* Clo, int m0, int n0)
{
  __shared__ float As[16][64];
  __shared__ float Bs[16][64];
  int tid=threadIdx.x;
  int tr=(tid>>4)*4, tc=(tid&15)*4;
  int aRow=tid>>2, aCol=(tid&3)*4;
  int bRow=tid>>4, bCol=(tid&15)*4;
  float acc[4][4];
  #pragma unroll
  for(int i=0;i<4;i++)
    #pragma unroll
    for(int j=0;j<4;j++) acc[i][j]=0.f;
  for(int k0=0;k0<128;k0+=16){
    float4 av=*(const float4*)(A+(size_t)(m0+aRow)*lda+k0+aCol);
    As[aCol+0][aRow]=av.x; As[aCol+1][aRow]=av.y;
    As[aCol+2][aRow]=av.z; As[aCol+3][aRow]=av.w;
    float4 bv=*(const float4*)(B+(size_t)(k0+bRow)*ldb+n0+bCol);
    *(float4*)(&Bs[bRow][bCol])=bv;
    __syncthreads();
    #pragma unroll
    for(int kk=0;kk<16;kk++){
      float af[4], bf[4];
      #pragma unroll
      for(int i=0;i<4;i++) af[i]=As[kk][tr+i];
      #pragma unroll
      for(int j=0;j<4;j++) bf[j]=Bs[kk][tc+j];
      #pragma unroll
      for(int i=0;i<4;i++)
        #pragma unroll
        for(int j=0;j<4;j++) acc[i][j]=fmaf(af[i],bf[j],acc[i][j]);
    }
    __syncthreads();
  }
  #pragma unroll
  for(int i=0;i<4;i++){
    size_t rowoff=(size_t)(m0+tr+i)*ldc + n0+tc;
    #pragma unroll
    for(int j=0;j<4;j++){
      float v=acc[i][j];
      if(bias) v+=bias[n0+tc+j];
      C[rowoff+j]=v;
      if(Chi){
        __nv_bfloat16 hi=__float2bfloat16(v);
        Chi[rowoff+j]=hi;
        Clo[rowoff+j]=__float2bfloat16(v-__bfloat162float(hi));
      }
    }
  }
}

__device__ void csr_build(const int* __restrict__ src, const int* __restrict__ dst){
  __shared__ int cnt[4096];
  __shared__ int png[4096];
  int t=threadIdx.x;
  for(int i=t;i<4096;i+=256) cnt[i]=0;
  __syncthreads();
  for(int e=t;e<EE;e+=256){
    atomicAdd(&cnt[dst[e]],1);
    atomicAdd(&cnt[2048+src[e]],1);
  }
  __syncthreads();
  for(int st=1;st<2048;st<<=1){
    for(int i=t;i<4096;i+=256){
      int v=cnt[i];
      if((i&2047)>=st) v+=cnt[i-st];
      png[i]=v;
    }
    __syncthreads();
    for(int i=t;i<4096;i+=256) cnt[i]=png[i];
    __syncthreads();
  }
  for(int i=t;i<4096;i+=256){
    int dir=i>>11, n=i&2047;
    int ex = n? cnt[i-1]:0;
    d_offs[dir*(NN+1)+n]=ex;
    png[i]=ex;
    if(n==2047) d_offs[dir*(NN+1)+2048]=cnt[i];
  }
  __syncthreads();
  for(int e=t;e<EE;e+=256){
    int p=atomicAdd(&png[dst[e]],1);       d_list[p]=e;
    int q=atomicAdd(&png[2048+src[e]],1);  d_list[EE+q]=e;
  }
  __syncthreads();
  for(int u=t;u<4096;u+=256){
    int dir=u>>11, n=u&2047;
    int* list=d_list+dir*EE;
    int s=d_offs[dir*(NN+1)+n], e=d_offs[dir*(NN+1)+n+1];
    for(int i=s+1;i<e;i++){
      int v=list[i]; int j=i-1;
      while(j>=s && list[j]>v){ list[j+1]=list[j]; j--; }
      list[j+1]=v;
    }
    const int* other = dir? dst : src;
    for(int i=s;i<e;i++) d_gl[dir*EE+i]=other[list[i]];
  }
}

__global__ void k_prep(
  const float* __restrict__ h_init0, const float* __restrict__ h_init1,
  const float* __restrict__ init_W, const float* __restrict__ init_b,
  const float* __restrict__ aggr_W, const float* __restrict__ gWhh,
  const float* __restrict__ gbhh, const float* __restrict__ gWih,
  const float* __restrict__ rW2,
  const int* __restrict__ src, const int* __restrict__ dst)
{
  int b = blockIdx.x;
  if(b < 256){
    // init GEMM: old grid (4,32,2) flattened
    int z = b>>7, r = b&127;
    int by = r>>2, bx = r&3;
    sgemm64(z? h_init0 : h_init1, 128,
            init_W+(size_t)z*128*256, 256, init_b+z*256,
            d_h+(size_t)z*2048*256, 256,
            d_hhi+(size_t)z*2048*256, d_hlo+(size_t)z*2048*256,
            by*64, bx*64);
  } else if(b < 8018){
    long idx=(long)(b-256)*256+threadIdx.x;
    if(idx<4096){
      int k=(int)(idx>>10), c=(int)(idx&1023);
      d_bias1[idx] = (c<256)? 0.f : gbhh[k*768 + (c-256)];
    } else if(idx<4096+1048576){
      long r=idx-4096;
      int k=(int)(r>>18);
      int rem=(int)(r&262143);
      int n=rem>>8, kk=rem&255;
      float v = (n<256)? aggr_W[(size_t)k*272*256 + (size_t)kk*256 + n]
                       : gWhh[(size_t)k*768*256 + (size_t)(n-256)*256 + kk];
      __nv_bfloat16 hi=__float2bfloat16(v);
      d_B1t_hi[r]=hi; d_B1t_lo[r]=__float2bfloat16(v-__bfloat162float(hi));
    } else if(idx<4096+1048576+786432){
      long r=idx-4096-1048576;
      float v=gWih[r];
      __nv_bfloat16 hi=__float2bfloat16(v);
      d_B2t_hi[r]=hi; d_B2t_lo[r]=__float2bfloat16(v-__bfloat162float(hi));
    } else if(idx<4096+1048576+786432+131072){
      long r=idx-4096-1048576-786432;
      int h=(int)(r>>16); int rem=(int)(r&65535);
      int n=rem>>8, kk=rem&255;
      float v=rW2[(size_t)h*65536 + (size_t)kk*256 + n];
      __nv_bfloat16 hi=__float2bfloat16(v);
      d_W2t_hi[r]=hi; d_W2t_lo[r]=__float2bfloat16(v-__bfloat162float(hi));
    } else if(idx<4096+1048576+786432+131072+16384){
      long r=idx-4096-1048576-786432-131072;
      int rr=(int)(r>>10), c=(int)(r&1023);
      int k=c>>8, col=c&255;
      d_EB[r]=aggr_W[(size_t)k*272*256 + (size_t)(256+rr)*256 + col];
    }
  } else {
    csr_build(src, dst);
  }
}

// ---------------- small fp32 GEMM (Q1/I1) ----------------
__global__ void __launch_bounds__(256,4) k_qi(const float* __restrict__ rW1){
  int z=blockIdx.z;
  sgemm64(d_pooled+(size_t)z*SS*DHH, 128,
           rW1+(size_t)(z>>1)*65536+(size_t)(z&1)*128*256, 256, nullptr,
           d_QI+(size_t)z*65536, 256, nullptr, nullptr,
           blockIdx.y*64, blockIdx.x*64);
}

// ---------------- gather (on-the-fly edge-attr projection) / gru ----------------
__global__ void __launch_bounds__(256,4) k_gather(int p,
  const float* __restrict__ ea, const float* __restrict__ aggr_b){
  int n=blockIdx.x, d=threadIdx.x;
  int half=n>>11, node=n&2047;
  int k=p+2*half;
  __shared__ float sEB[16*256];
  __shared__ float sea[32*16];
  #pragma unroll
  for(int j=0;j<16;j++) sEB[j*256+d] = d_EB[j*1024 + k*256 + d];
  const int* offs=d_offs+p*(NN+1);
  const int* list=d_list+p*EE;
  const int* gl  =d_gl  +p*EE;
  int s=offs[node], e=offs[node+1];
  const float* hW = d_G1 + (size_t)half*2048*1024;
  float bias = aggr_b[k*256+d];
  float acc=0.f;
  __syncthreads();
  for(int i0=s; i0<e; i0+=32){
    int cnt = e-i0; if(cnt>32) cnt=32;
    for(int u=d; u<cnt*16; u+=256)
      sea[u] = ea[(size_t)list[i0+(u>>4)]*16 + (u&15)];
    __syncthreads();
    for(int q=0;q<cnt;q++){
      int o = gl[i0+q];
      float v = hW[(size_t)o*1024+d] + bias;
      #pragma unroll
      for(int j=0;j<16;j++) v = fmaf(sea[q*16+j], sEB[j*256+d], v);
      acc += fmaxf(v, 0.f);
    }
    __syncthreads();
  }
  __nv_bfloat16 hi=__float2bfloat16(acc);
  d_agghi[n*H2C+d]=hi;
  d_agglo[n*H2C+d]=__float2bfloat16(acc-__bfloat162float(hi));
}

__global__ void k_gru(){
  int n=blockIdx.x, d=threadIdx.x;
  const float* gi=d_gi+(size_t)n*G3C;
  const float* gh=d_G1+(size_t)n*1024+256;
  float ir=gi[d], iz=gi[H2C+d], inn=gi[2*H2C+d];
  float hr=gh[d], hz=gh[H2C+d], hn=gh[2*H2C+d];
  float r=1.f/(1.f+expf(-(ir+hr)));
  float z=1.f/(1.f+expf(-(iz+hz)));
  float nn=tanhf(inn + r*hn);
  float hv=d_h[n*H2C+d];
  float nv=(1.f-z)*nn + z*hv;
  d_h[n*H2C+d]=nv;
  __nv_bfloat16 hi=__float2bfloat16(nv);
  d_hhi[n*H2C+d]=hi;
  d_hlo[n*H2C+d]=__float2bfloat16(nv-__bfloat162float(hi));
}

// ---------------- pooling (3 kernels) ----------------
__global__ void k_poolscore(const float* __restrict__ pW1,
                            const float* __restrict__ pb1,
                            const float* __restrict__ pv){
  int p=blockIdx.y, x8=blockIdx.x, j=threadIdx.x;
  __shared__ float xs[8][DHH];
  int coff=(p<2)? 0 : DHH;
  #pragma unroll
  for(int q=0;q<8;q++){
    int x=x8*8+q;
    if(x<NN+8){
      bool isB = x>=NN;
      int node = isB? (SPECIAL + x - NN) : x;
      const float* hb = isB? (d_h + (size_t)2048*H2C) : d_h;
      xs[q][j]=hb[(size_t)node*H2C+coff+j];
    } else xs[q][j]=0.f;
  }
  __syncthreads();
  const float* W = pW1 + p*DHH*DHH;
  float bb = pb1[p*DHH+j];
  float acc[8];
  #pragma unroll
  for(int q=0;q<8;q++) acc[q]=bb;
  for(int d=0;d<DHH;d++){
    float w = W[d*DHH+j];
    #pragma unroll
    for(int q=0;q<8;q++) acc[q]=fmaf(xs[q][d], w, acc[q]);
  }
  float pvj = pv[p*DHH+j];
  #pragma unroll
  for(int q=0;q<8;q++){
    float y = tanhf(acc[q])*pvj;
    float s = blkSum<128>(y);
    if(j==0){
      int x=x8*8+q;
      if(x<NN) d_tA[p*NN+x]=s;
      else if(x<NN+8) d_tB[p*8+(x-NN)]=s;
    }
  }
}

__global__ void k_poolpart(){
  int c=blockIdx.x, p=blockIdx.y, t=threadIdx.x;
  float mx=-1e30f;
  for(int n=t;n<NN;n+=128) mx=fmaxf(mx, d_tA[p*NN+n]);
  if(t<8) mx=fmaxf(mx, d_tB[p*8+t]);
  float M = blkMax<128>(mx);
  if(c==0 && t==0) d_Mx[p]=M;
  int n0=c*128;
  int lim = SPECIAL - n0; if(lim>128) lim=128; if(lim<0) lim=0;
  int coff=(p<2)? 0 : DHH;
  __shared__ float ws[128];
  float w = (t<lim)? expf(d_tA[p*NN+n0+t]-M) : 0.f;
  ws[t]=w;
  float den = blkSum<128>(w);
  float num=0.f;
  for(int i=0;i<lim;i++)
    num = fmaf(ws[i], d_h[(size_t)(n0+i)*H2C+coff+t], num);
  d_pNum[(p*16+c)*DHH+t]=num;
  if(t==0) d_pDen[p*16+c]=den;
}

__global__ void k_poolstates(){
  int s=blockIdx.x, p=blockIdx.y, d=threadIdx.x;
  int coff=(p<2)? 0 : DHH;
  float M=d_Mx[p];
  float num=0.f, den=0.f;
  #pragma unroll
  for(int c=0;c<16;c++){
    num += d_pNum[(p*16+c)*DHH+d];
    den += d_pDen[p*16+c];
  }
  #pragma unroll
  for(int j=0;j<8;j++){
    int node=SPECIAL+j;
    int bit=(s>>(7-j))&1;
    float tv = bit? d_tB[p*8+j] : d_tA[p*NN+node];
    float w = expf(tv-M);
    const float* h = bit? (d_h+(size_t)2048*H2C) : d_h;
    num = fmaf(w, h[(size_t)node*H2C+coff+d], num);
    den += w;
  }
  d_pooled[(p*SS+s)*DHH + d] = num/den;
}

// ---------------- outputs ----------------
__global__ void k_out(const float* __restrict__ finite,
                      const float* __restrict__ trans,
                      float* __restrict__ out){
  int a=blockIdx.x, b=threadIdx.x;
  int idx=a*256+b;
  out[idx]=d_ho[idx];
  out[65536+idx]= (finite[idx]>0.f)?1.f:0.f;
  out[3*65536+idx]=trans[idx];
  float x=d_ho[65536+idx];
  float M=blkMax<256>(x);
  float e=expf(x-M);
  float sum=blkSum<256>(e);
  out[2*65536 + idx] = x - M - logf(sum);
}

// ---------------- host ----------------
static float* symf(const void* s){ void* p=nullptr; cudaGetSymbolAddress(&p, s); return (float*)p; }
static __nv_bfloat16* symb(const void* s){ void* p=nullptr; cudaGetSymbolAddress(&p, s); return (__nv_bfloat16*)p; }

extern "C" void kernel_launch(void* const* d_in, const int* in_sizes, int n_in,
                              void* d_out, int out_size){
  const int*   edge_index=(const int*)d_in[0];
  const float* edge_attr =(const float*)d_in[1];
  const float* h_init0   =(const float*)d_in[2];
  const float* h_init1   =(const float*)d_in[3];
  const float* finite    =(const float*)d_in[4];
  const float* trans     =(const float*)d_in[5];
  const float* init_W    =(const float*)d_in[6];
  const float* init_b    =(const float*)d_in[7];
  const float* aggr_W    =(const float*)d_in[8];
  const float* aggr_b    =(const float*)d_in[9];
  const float* gWih      =(const float*)d_in[10];
  const float* gWhh      =(const float*)d_in[11];
  const float* gbih      =(const float*)d_in[12];
  const float* gbhh      =(const float*)d_in[13];
  const float* pW1       =(const float*)d_in[14];
  const float* pb1       =(const float*)d_in[15];
  const float* pv        =(const float*)d_in[16];
  const float* rW1       =(const float*)d_in[17];
  const float* rb1       =(const float*)d_in[18];
  const float* rg1       =(const float*)d_in[19];
  const float* rbe1      =(const float*)d_in[20];
  const float* rW2       =(const float*)d_in[21];
  const float* rb2       =(const float*)d_in[22];
  const float* rg2       =(const float*)d_in[23];
  const float* rbe2      =(const float*)d_in[24];
  const float* rW3       =(const float*)d_in[25];
  const float* rb3       =(const float*)d_in[26];
  const int* src=edge_index;
  const int* dst=edge_index+EE;
  float* out=(float*)d_out;

  float* P_bias1= symf(d_bias1);
  float* P_G1   = symf(d_G1);
  float* P_gi   = symf(d_gi);
  __nv_bfloat16* P_hhi  = symb(d_hhi);
  __nv_bfloat16* P_hlo  = symb(d_hlo);
  __nv_bfloat16* P_ahi  = symb(d_agghi);
  __nv_bfloat16* P_alo  = symb(d_agglo);
  __nv_bfloat16* P_B1h  = symb(d_B1t_hi);
  __nv_bfloat16* P_B1l  = symb(d_B1t_lo);
  __nv_bfloat16* P_B2h  = symb(d_B2t_hi);
  __nv_bfloat16* P_B2l  = symb(d_B2t_lo);

  cudaFuncSetAttribute(hmma, cudaFuncAttributeMaxDynamicSharedMemorySize, HSMEM);
  cudaFuncSetAttribute(k_ro, cudaFuncAttributeMaxDynamicSharedMemorySize, ROSMEM);

  // prep: init GEMM + weight pack + CSR concurrently in ONE kernel
  k_prep<<<8019,256>>>(h_init0, h_init1, init_W, init_b,
                       aggr_W, gWhh, gbhh, gWih, rW2, src, dst);

  // message passing
  for(int r=0;r<4;r++){
    for(int p=0;p<2;p++){
      hmma<<<dim3(8,32),256,HSMEM>>>(2048,
        P_hhi, P_hlo,
        P_B1h+(size_t)p*262144, P_B1l+(size_t)p*262144,
        P_B1h+(size_t)(p+2)*262144, P_B1l+(size_t)(p+2)*262144,
        P_bias1+p*1024, P_bias1+(p+2)*1024, P_G1, 1024);
      k_gather<<<NB,256>>>(p, edge_attr, aggr_b);
      hmma<<<dim3(6,32),256,HSMEM>>>(2048,
        P_ahi, P_alo,
        P_B2h+(size_t)p*196608, P_B2l+(size_t)p*196608,
        P_B2h+(size_t)(p+2)*196608, P_B2l+(size_t)(p+2)*196608,
        gbih+p*G3C, gbih+(p+2)*G3C, P_gi, G3C);
      k_gru<<<NB,256>>>();
    }
  }

  // pooling (3 kernels)
  k_poolscore<<<dim3(257,4),128>>>(pW1,pb1,pv);
  k_poolpart<<<dim3(16,4),128>>>();
  k_poolstates<<<dim3(SS,4),128>>>();

  // readout
  k_qi<<<dim3(4,4,4),256>>>(rW1);
  k_ro<<<dim3(1024,2),256,ROSMEM>>>(rb1,rg1,rbe1,rb2,rg2,rbe2,rW3,rb3);

  // outputs
  k_out<<<SS,256>>>(finite,trans,out);
}

// round 15
// speedup vs baseline: 1.1476x; 1.1476x over previous
#include <cuda_runtime.h>
#include <cuda_bf16.h>
#include <cstdint>
#include <math.h>

#define NN 2048
#define EE 16384
#define SS 256
#define DHH 128
#define H2C 256
#define DMC 256
#define G3C 768
#define SPECIAL 2040
#define NB 4096

// ---------------- device scratch ----------------
__device__ __align__(256) float d_h[NB*H2C];
__device__ __align__(256) float d_EB[16*1024];
__device__ __align__(256) float d_bias1[4*1024];
__device__ __align__(256) float d_G1[NB*1024];
__device__ __align__(256) float d_gi[NB*G3C];
__device__ __align__(256) __nv_bfloat16 d_hhi[NB*H2C];
__device__ __align__(256) __nv_bfloat16 d_hlo[NB*H2C];
__device__ __align__(256) __nv_bfloat16 d_agghi[NB*H2C];
__device__ __align__(256) __nv_bfloat16 d_agglo[NB*H2C];
__device__ __align__(256) __nv_bfloat16 d_B1t_hi[4*1024*256];
__device__ __align__(256) __nv_bfloat16 d_B1t_lo[4*1024*256];
__device__ __align__(256) __nv_bfloat16 d_B2t_hi[4*768*256];
__device__ __align__(256) __nv_bfloat16 d_B2t_lo[4*768*256];
__device__ __align__(256) __nv_bfloat16 d_W2t_hi[2*256*256];
__device__ __align__(256) __nv_bfloat16 d_W2t_lo[2*256*256];
__device__ int   d_offs[2*(NN+1)];
__device__ int   d_list[2*EE];
__device__ int   d_gl[2*EE];
__device__ float d_tA[4*NN];
__device__ float d_tB[4*8];
__device__ float d_Mx[4];
__device__ float d_pNum[4*16*DHH];
__device__ float d_pDen[4*16];
__device__ __align__(256) float d_pooled[4*SS*DHH];
__device__ __align__(256) float d_QI[4*SS*DMC];
__device__ float d_ho[2*SS*SS];

// ---------------- helpers ----------------
__device__ __forceinline__ uint32_t smem_u32(const void* p){
  uint32_t a; asm("{ .reg .u64 t; cvta.to.shared.u64 t, %1; cvt.u32.u64 %0, t; }" : "=r"(a) : "l"(p)); return a;
}
__device__ __forceinline__ void mma16816(float* c, const uint32_t* a, const uint32_t* b){
  asm volatile(
    "mma.sync.aligned.m16n8k16.row.col.f32.bf16.bf16.f32 "
    "{%0,%1,%2,%3}, {%4,%5,%6,%7}, {%8,%9}, {%0,%1,%2,%3};"
    : "+f"(c[0]), "+f"(c[1]), "+f"(c[2]), "+f"(c[3])
    : "r"(a[0]), "r"(a[1]), "r"(a[2]), "r"(a[3]), "r"(b[0]), "r"(b[1]));
}
__device__ __forceinline__ void ldmx4(uint32_t* r, uint32_t addr){
  asm volatile("ldmatrix.sync.aligned.m8n8.x4.shared.b16 {%0,%1,%2,%3}, [%4];"
    : "=r"(r[0]), "=r"(r[1]), "=r"(r[2]), "=r"(r[3]) : "r"(addr));
}

// ---------------- split-bf16 HMMA GEMM (loop GEMMs) ----------------
#define HSMEM 65536
__device__ __forceinline__ void h_load(int tid, uint32_t base,
  const __nv_bfloat16* Ahi, const __nv_bfloat16* Alo,
  const __nv_bfloat16* Bhi, const __nv_bfloat16* Blo,
  int m0, int n0, int c)
{
  const __nv_bfloat16* srcs[4] = { Ahi, Alo, Bhi, Blo };
  int rows0[4] = { m0, m0, n0, n0 };
  #pragma unroll
  for(int a=0;a<4;a++){
    const __nv_bfloat16* S = srcs[a];
    uint32_t dbase = base + a*8192u;
    int row0 = rows0[a];
    #pragma unroll
    for(int i=0;i<2;i++){
      int u = tid + i*256;
      int r = u>>2, col = u&3;
      const void* src = S + (size_t)(row0+r)*256 + c*32 + col*8;
      uint32_t dst = dbase + (uint32_t)(r*64) + (uint32_t)((col ^ ((r>>1)&3))<<4);
      asm volatile("cp.async.cg.shared.global [%0], [%1], 16;" :: "r"(dst), "l"(src));
    }
  }
  asm volatile("cp.async.commit_group;");
}

__global__ void __launch_bounds__(256,2) hmma(int Msplit,
  const __nv_bfloat16* __restrict__ Ahi, const __nv_bfloat16* __restrict__ Alo,
  const __nv_bfloat16* __restrict__ Bhi0, const __nv_bfloat16* __restrict__ Blo0,
  const __nv_bfloat16* __restrict__ Bhi1, const __nv_bfloat16* __restrict__ Blo1,
  const float* __restrict__ bias0, const float* __restrict__ bias1,
  float* __restrict__ C, int ldc)
{
  extern __shared__ char smem[];
  uint32_t sb = smem_u32(smem);
  int tid=threadIdx.x, lane=tid&31, wid=tid>>5;
  int m0=blockIdx.y*128, n0=blockIdx.x*128;
  const __nv_bfloat16* Bhi=(m0<Msplit)?Bhi0:Bhi1;
  const __nv_bfloat16* Blo=(m0<Msplit)?Blo0:Blo1;
  const float* bias=(m0<Msplit)?bias0:bias1;
  int wm = wid>>2, wn = wid&3;

  float acc[4][4][4];
  #pragma unroll
  for(int i=0;i<4;i++)
    #pragma unroll
    for(int j=0;j<4;j++)
      #pragma unroll
      for(int k=0;k<4;k++) acc[i][j][k]=0.f;

  h_load(tid, sb, Ahi, Alo, Bhi, Blo, m0, n0, 0);

  for(int c=0;c<8;c++){
    uint32_t buf = sb + (uint32_t)(c&1)*32768u;
    asm volatile("cp.async.wait_group 0;");
    __syncthreads();
    if(c<7)
      h_load(tid, sb + (uint32_t)((c+1)&1)*32768u, Ahi, Alo, Bhi, Blo, m0, n0, c+1);

    uint32_t aHB=buf, aLB=buf+8192u, bHB=buf+16384u, bLB=buf+24576u;
    #pragma unroll
    for(int ks=0; ks<2; ks++){
      uint32_t bh[4][2], bl[4][2];
      {
        int rn = wn*32 + ((lane>>4)<<3) + (lane&7);
        int cB = 2*ks + ((lane>>3)&1);
        #pragma unroll
        for(int nip=0; nip<2; nip++){
          int r = rn + nip*16;
          uint32_t off = (uint32_t)(r*64) + (uint32_t)((cB ^ ((r>>1)&3))<<4);
          uint32_t t[4];
          ldmx4(t, bHB + off);
          bh[2*nip][0]=t[0]; bh[2*nip][1]=t[1]; bh[2*nip+1][0]=t[2]; bh[2*nip+1][1]=t[3];
          ldmx4(t, bLB + off);
          bl[2*nip][0]=t[0]; bl[2*nip][1]=t[1]; bl[2*nip+1][0]=t[2]; bl[2*nip+1][1]=t[3];
        }
      }
      uint32_t af[4][4];
      int rA = lane&15, cA = 2*ks + (lane>>4);
      #pragma unroll
      for(int mi=0;mi<4;mi++){
        int r = wm*64 + mi*16 + rA;
        uint32_t off = (uint32_t)(r*64) + (uint32_t)((cA ^ ((r>>1)&3))<<4);
        ldmx4(af[mi], aHB + off);
      }
      #pragma unroll
      for(int mi=0;mi<4;mi++)
        #pragma unroll
        for(int ni=0;ni<4;ni++)
          mma16816(acc[mi][ni], af[mi], bh[ni]);   // hi*hi
      #pragma unroll
      for(int mi=0;mi<4;mi++)
        #pragma unroll
        for(int ni=0;ni<4;ni++)
          mma16816(acc[mi][ni], af[mi], bl[ni]);   // hi*lo
      #pragma unroll
      for(int mi=0;mi<4;mi++){
        int r = wm*64 + mi*16 + rA;
        uint32_t off = (uint32_t)(r*64) + (uint32_t)((cA ^ ((r>>1)&3))<<4);
        ldmx4(af[mi], aLB + off);
      }
      #pragma unroll
      for(int mi=0;mi<4;mi++)
        #pragma unroll
        for(int ni=0;ni<4;ni++)
          mma16816(acc[mi][ni], af[mi], bh[ni]);   // lo*hi
    }
  }

  int gr = lane>>2, gc = (lane&3)*2;
  #pragma unroll
  for(int mi=0;mi<4;mi++){
    int r1 = m0 + wm*64 + mi*16 + gr;
    #pragma unroll
    for(int ni=0;ni<4;ni++){
      int col = n0 + wn*32 + ni*8 + gc;
      float b0 = bias[col], b1 = bias[col+1];
      float2 v0 = make_float2(acc[mi][ni][0]+b0, acc[mi][ni][1]+b1);
      float2 v1 = make_float2(acc[mi][ni][2]+b0, acc[mi][ni][3]+b1);
      *(float2*)(C + (size_t)r1*ldc + col) = v0;
      *(float2*)(C + (size_t)(r1+8)*ldc + col) = v1;
    }
  }
}

// ---------------- fused readout (96KB smem -> 2 CTAs/SM) ----------------
#define ROSMEM 98304
__global__ void __launch_bounds__(256,2) k_ro(
  const float* __restrict__ rb1, const float* __restrict__ rg1, const float* __restrict__ rbe1,
  const float* __restrict__ rb2, const float* __restrict__ rg2, const float* __restrict__ rbe2,
  const float* __restrict__ rW3, const float* __restrict__ rb3)
{
  extern __shared__ char smem[];
  uint32_t sb = smem_u32(smem);
  int h = blockIdx.y;
  int tid=threadIdx.x, lane=tid&31, wid=tid>>5;
  int wm=wid>>2, wn=wid&3;
  int row0 = blockIdx.x*64;

  const float* Q1 = d_QI + (size_t)(2*h)*65536;
  const float* I1 = d_QI + (size_t)(2*h+1)*65536;
  const float* b1 = rb1 + h*256;
  const float* g1 = rg1 + h*256;
  const float* be1 = rbe1 + h*256;
  const __nv_bfloat16* Wh = d_W2t_hi + (size_t)h*65536;
  const __nv_bfloat16* Wl = d_W2t_lo + (size_t)h*65536;

  #define RO_BLOAD(cc) do{ \
    uint32_t base_ = sb + 65536u; \
    _Pragma("unroll") \
    for(int i_=0;i_<4;i_++){ \
      int u_ = tid + i_*256; int r_=u_>>2, col_=u_&3; \
      const void* sh_ = Wh + (size_t)r_*256 + (cc)*32 + col_*8; \
      const void* sl_ = Wl + (size_t)r_*256 + (cc)*32 + col_*8; \
      uint32_t d_ = base_ + (uint32_t)(r_*64) + (uint32_t)((col_ ^ ((r_>>1)&3))<<4); \
      asm volatile("cp.async.cg.shared.global [%0], [%1], 16;" :: "r"(d_), "l"(sh_)); \
      asm volatile("cp.async.cg.shared.global [%0], [%1], 16;" :: "r"(d_+16384u), "l"(sl_)); \
    } \
    asm volatile("cp.async.commit_group;"); \
  }while(0)

  RO_BLOAD(0);

  {
    int rl = tid>>2, cg = tid&3;
    int grow = row0 + rl;
    int a = grow>>8, b = grow&255;
    const float* qrow = Q1 + (size_t)b*256 + cg*64;
    const float* irow = I1 + (size_t)a*256 + cg*64;
    const float* brow = b1 + cg*64;
    float s1=0.f, s2=0.f;
    #pragma unroll 8
    for(int i=0;i<64;i++){
      float z = qrow[i]+irow[i]+brow[i];
      s1+=z; s2+=z*z;
    }
    s1 += __shfl_xor_sync(0xffffffffu,s1,1); s2 += __shfl_xor_sync(0xffffffffu,s2,1);
    s1 += __shfl_xor_sync(0xffffffffu,s1,2); s2 += __shfl_xor_sync(0xffffffffu,s2,2);
    float mean = s1*(1.f/256.f);
    float rstd = rsqrtf(s2*(1.f/256.f)-mean*mean+1e-5f);
    const float* g1c = g1 + cg*64;
    const float* be1c = be1 + cg*64;
    #pragma unroll
    for(int g=0; g<8; g++){
      uint32_t hi4[4], lo4[4];
      #pragma unroll
      for(int ii=0; ii<4; ii++){
        int j = g*8 + 2*ii;
        float z0 = qrow[j]+irow[j]+brow[j];
        float z1 = qrow[j+1]+irow[j+1]+brow[j+1];
        float v0 = fmaxf((z0-mean)*rstd*g1c[j]+be1c[j], 0.f);
        float v1 = fmaxf((z1-mean)*rstd*g1c[j+1]+be1c[j+1], 0.f);
        __nv_bfloat16 h0=__float2bfloat16(v0), h1=__float2bfloat16(v1);
        __nv_bfloat16 l0=__float2bfloat16(v0-__bfloat162float(h0));
        __nv_bfloat16 l1=__float2bfloat16(v1-__bfloat162float(h1));
        hi4[ii] = ((uint32_t)__bfloat16_as_ushort(h1)<<16) | (uint32_t)__bfloat16_as_ushort(h0);
        lo4[ii] = ((uint32_t)__bfloat16_as_ushort(l1)<<16) | (uint32_t)__bfloat16_as_ushort(l0);
      }
      int c16 = cg*8+g;
      uint32_t off = (uint32_t)(rl*512) + (uint32_t)((c16 ^ (rl&7))<<4);
      *(uint4*)(smem + off) = make_uint4(hi4[0],hi4[1],hi4[2],hi4[3]);
      *(uint4*)(smem + 32768 + off) = make_uint4(lo4[0],lo4[1],lo4[2],lo4[3]);
    }
  }
  __syncthreads();

  float acc[2][8][4];
  #pragma unroll
  for(int i=0;i<2;i++)
    #pragma unroll
    for(int j=0;j<8;j++)
      #pragma unroll
      for(int k=0;k<4;k++) acc[i][j][k]=0.f;

  for(int c=0;c<8;c++){
    asm volatile("cp.async.wait_group 0;");
    __syncthreads();
    uint32_t bB = sb + 65536u;
    #pragma unroll
    for(int ks=0;ks<2;ks++){
      uint32_t ahi[2][4], alo[2][4];
      int rA = lane&15;
      int c16 = c*4 + ks*2 + (lane>>4);
      #pragma unroll
      for(int mi=0;mi<2;mi++){
        int row = wm*32 + mi*16 + rA;
        uint32_t off = (uint32_t)(row*512) + (uint32_t)((c16 ^ (row&7))<<4);
        ldmx4(ahi[mi], sb + off);
        ldmx4(alo[mi], sb + 32768u + off);
      }
      uint32_t bh[8][2], bl[8][2];
      int rn = wn*64 + ((lane>>4)<<3) + (lane&7);
      int cB = 2*ks + ((lane>>3)&1);
      #pragma unroll
      for(int nip=0;nip<4;nip++){
        int r = rn + nip*16;
        uint32_t off = (uint32_t)(r*64) + (uint32_t)((cB ^ ((r>>1)&3))<<4);
        uint32_t t[4];
        ldmx4(t, bB + off);
        bh[2*nip][0]=t[0]; bh[2*nip][1]=t[1]; bh[2*nip+1][0]=t[2]; bh[2*nip+1][1]=t[3];
        ldmx4(t, bB + 16384u + off);
        bl[2*nip][0]=t[0]; bl[2*nip][1]=t[1]; bl[2*nip+1][0]=t[2]; bl[2*nip+1][1]=t[3];
      }
      #pragma unroll
      for(int mi=0;mi<2;mi++)
        #pragma unroll
        for(int ni=0;ni<8;ni++)
          mma16816(acc[mi][ni], ahi[mi], bh[ni]);
      #pragma unroll
      for(int mi=0;mi<2;mi++)
        #pragma unroll
        for(int ni=0;ni<8;ni++)
          mma16816(acc[mi][ni], ahi[mi], bl[ni]);
      #pragma unroll
      for(int mi=0;mi<2;mi++)
        #pragma unroll
        for(int ni=0;ni<8;ni++)
          mma16816(acc[mi][ni], alo[mi], bh[ni]);
    }
    __syncthreads();
    if(c<7) RO_BLOAD(c+1);
  }

  const float* b2 = rb2 + h*256;
  const float* g2 = rg2 + h*256;
  const float* be2 = rbe2 + h*256;
  const float* W3 = rW3 + h*256;
  float* ps = (float*)smem;
  float* pq = ps + 256;
  float* pd = pq + 256;
  float* mn2 = pd + 256;
  float* rs2 = mn2 + 64;
  int gr=lane>>2, gc=(lane&3)*2;
  #pragma unroll
  for(int mi=0;mi<2;mi++){
    #pragma unroll
    for(int half=0;half<2;half++){
      float s=0.f,q=0.f;
      #pragma unroll
      for(int ni=0;ni<8;ni++){
        int col = wn*64 + ni*8 + gc;
        float y0 = acc[mi][ni][half*2+0] + b2[col];
        float y1 = acc[mi][ni][half*2+1] + b2[col+1];
        s += y0+y1; q += y0*y0+y1*y1;
      }
      s += __shfl_xor_sync(0xffffffffu,s,1); q += __shfl_xor_sync(0xffffffffu,q,1);
      s += __shfl_xor_sync(0xffffffffu,s,2); q += __shfl_xor_sync(0xffffffffu,q,2);
      if((lane&3)==0){
        int rl2 = wm*32+mi*16+half*8+gr;
        ps[rl2*4+wn]=s; pq[rl2*4+wn]=q;
      }
    }
  }
  __syncthreads();
  if(tid<64){
    float s=ps[tid*4]+ps[tid*4+1]+ps[tid*4+2]+ps[tid*4+3];
    float q=pq[tid*4]+pq[tid*4+1]+pq[tid*4+2]+pq[tid*4+3];
    float m=s*(1.f/256.f);
    mn2[tid]=m; rs2[tid]=rsqrtf(q*(1.f/256.f)-m*m+1e-5f);
  }
  __syncthreads();
  #pragma unroll
  for(int mi=0;mi<2;mi++){
    #pragma unroll
    for(int half=0;half<2;half++){
      int rl2 = wm*32+mi*16+half*8+gr;
      float m=mn2[rl2], rs=rs2[rl2];
      float dsum=0.f;
      #pragma unroll
      for(int ni=0;ni<8;ni++){
        int col = wn*64 + ni*8 + gc;
        float y0 = acc[mi][ni][half*2+0] + b2[col];
        float y1 = acc[mi][ni][half*2+1] + b2[col+1];
        float u0 = fmaxf((y0-m)*rs*g2[col]+be2[col], 0.f);
        float u1 = fmaxf((y1-m)*rs*g2[col+1]+be2[col+1], 0.f);
        dsum += u0*W3[col] + u1*W3[col+1];
      }
      dsum += __shfl_xor_sync(0xffffffffu,dsum,1);
      dsum += __shfl_xor_sync(0xffffffffu,dsum,2);
      if((lane&3)==0) pd[rl2*4+wn]=dsum;
    }
  }
  __syncthreads();
  if(tid<64)
    d_ho[(size_t)h*65536 + row0 + tid] =
      pd[tid*4]+pd[tid*4+1]+pd[tid*4+2]+pd[tid*4+3] + rb3[h];
}

// ---------------- block reductions ----------------
template<int NT>
__device__ __forceinline__ float blkSum(float v){
  __shared__ float sh[NT/32];
  __shared__ float tot;
  int lane=threadIdx.x&31, w=threadIdx.x>>5;
  #pragma unroll
  for(int o=16;o>0;o>>=1) v+=__shfl_down_sync(0xffffffffu,v,o);
  if(lane==0) sh[w]=v;
  __syncthreads();
  if(w==0){
    float x=(lane<NT/32)? sh[lane] : 0.f;
    #pragma unroll
    for(int o=(NT/32)/2;o>0;o>>=1) x+=__shfl_down_sync(0xffffffffu,x,o);
    if(lane==0) tot=x;
  }
  __syncthreads();
  return tot;
}
template<int NT>
__device__ __forceinline__ float blkMax(float v){
  __shared__ float sh[NT/32];
  __shared__ float tot;
  int lane=threadIdx.x&31, w=threadIdx.x>>5;
  #pragma unroll
  for(int o=16;o>0;o>>=1) v=fmaxf(v,__shfl_down_sync(0xffffffffu,v,o));
  if(lane==0) sh[w]=v;
  __syncthreads();
  if(w==0){
    float x=(lane<NT/32)? sh[lane] : -1e30f;
    #pragma unroll
    for(int o=(NT/32)/2;o>0;o>>=1) x=fmaxf(x,__shfl_down_sync(0xffffffffu,x,o));
    if(lane==0) tot=x;
  }
  __syncthreads();
  return tot;
}

// ---------------- small fp32 GEMM body (64x64 tiles, K=128) ----------------
__device__ __forceinline__ void sgemm64(
  const float* __restrict__ A,int lda,const float* __restrict__ B,int ldb,
  const float* __restrict__ bias, float* __restrict__ C,int ldc,
  __nv_bfloat16* Chi, __nv_bfloat16* Clo, int m0, int n0)
{
  __shared__ float As[16][64];
  __shared__ float Bs[16][64];
  int tid=threadIdx.x;
  int tr=(tid>>4)*4, tc=(tid&15)*4;
  int aRow=tid>>2, aCol=(tid&3)*4;
  int bRow=tid>>4, bCol=(tid&15)*4;
  float acc[4][4];
  #pragma unroll
  for(int i=0;i<4;i++)
    #pragma unroll
    for(int j=0;j<4;j++) acc[i][j]=0.f;
  for(int k0=0;k0<128;k0+=16){
    float4 av=*(const float4*)(A+(size_t)(m0+aRow)*lda+k0+aCol);
    As[aCol+0][aRow]=av.x; As[aCol+1][aRow]=av.y;
    As[aCol+2][aRow]=av.z; As[aCol+3][aRow]=av.w;
    float4 bv=*(const float4*)(B+(size_t)(k0+bRow)*ldb+n0+bCol);
    *(float4*)(&Bs[bRow][bCol])=bv;
    __syncthreads();
    #pragma unroll
    for(int kk=0;kk<16;kk++){
      float af[4], bf[4];
      #pragma unroll
      for(int i=0;i<4;i++) af[i]=As[kk][tr+i];
      #pragma unroll
      for(int j=0;j<4;j++) bf[j]=Bs[kk][tc+j];
      #pragma unroll
      for(int i=0;i<4;i++)
        #pragma unroll
        for(int j=0;j<4;j++) acc[i][j]=fmaf(af[i],bf[j],acc[i][j]);
    }
    __syncthreads();
  }
  #pragma unroll
  for(int i=0;i<4;i++){
    size_t rowoff=(size_t)(m0+tr+i)*ldc + n0+tc;
    #pragma unroll
    for(int j=0;j<4;j++){
      float v=acc[i][j];
      if(bias) v+=bias[n0+tc+j];
      C[rowoff+j]=v;
      if(Chi){
        __nv_bfloat16 hi=__float2bfloat16(v);
        Chi[rowoff+j]=hi;
        Clo[rowoff+j]=__float2bfloat16(v-__bfloat162float(hi));
      }
    }
  }
}

__global__ void __launch_bounds__(256,4) k_init(
  const float* __restrict__ h_init0, const float* __restrict__ h_init1,
  const float* __restrict__ init_W, const float* __restrict__ init_b)
{
  int z=blockIdx.z;
  sgemm64(z? h_init0 : h_init1, 128,
           init_W+(size_t)z*128*256, 256, init_b+z*256,
           d_h+(size_t)z*2048*256, 256,
           d_hhi+(size_t)z*2048*256, d_hlo+(size_t)z*2048*256,
           blockIdx.y*64, blockIdx.x*64);
}

__global__ void __launch_bounds__(256,4) k_qi(const float* __restrict__ rW1){
  int z=blockIdx.z;
  sgemm64(d_pooled+(size_t)z*SS*DHH, 128,
           rW1+(size_t)(z>>1)*65536+(size_t)(z&1)*128*256, 256, nullptr,
           d_QI+(size_t)z*65536, 256, nullptr, nullptr,
           blockIdx.y*64, blockIdx.x*64);
}

// ---------------- pack all weights ----------------
__global__ void k_packAll(const float* __restrict__ aggr_W,
                          const float* __restrict__ gWhh,
                          const float* __restrict__ gbhh,
                          const float* __restrict__ gWih,
                          const float* __restrict__ rW2){
  long idx=(long)blockIdx.x*256+threadIdx.x;
  if(idx<4096){
    int k=(int)(idx>>10), c=(int)(idx&1023);
    d_bias1[idx] = (c<256)? 0.f : gbhh[k*768 + (c-256)];
  } else if(idx<4096+1048576){
    long r=idx-4096;
    int k=(int)(r>>18);
    int rem=(int)(r&262143);
    int n=rem>>8, kk=rem&255;
    float v = (n<256)? aggr_W[(size_t)k*272*256 + (size_t)kk*256 + n]
                     : gWhh[(size_t)k*768*256 + (size_t)(n-256)*256 + kk];
    __nv_bfloat16 hi=__float2bfloat16(v);
    d_B1t_hi[r]=hi; d_B1t_lo[r]=__float2bfloat16(v-__bfloat162float(hi));
  } else if(idx<4096+1048576+786432){
    long r=idx-4096-1048576;
    float v=gWih[r];
    __nv_bfloat16 hi=__float2bfloat16(v);
    d_B2t_hi[r]=hi; d_B2t_lo[r]=__float2bfloat16(v-__bfloat162float(hi));
  } else if(idx<4096+1048576+786432+131072){
    long r=idx-4096-1048576-786432;
    int h=(int)(r>>16); int rem=(int)(r&65535);
    int n=rem>>8, kk=rem&255;
    float v=rW2[(size_t)h*65536 + (size_t)kk*256 + n];
    __nv_bfloat16 hi=__float2bfloat16(v);
    d_W2t_hi[r]=hi; d_W2t_lo[r]=__float2bfloat16(v-__bfloat162float(hi));
  } else if(idx<4096+1048576+786432+131072+16384){
    long r=idx-4096-1048576-786432-131072;
    int rr=(int)(r>>10), c=(int)(r&1023);
    int k=c>>8, col=c&255;
    d_EB[r]=aggr_W[(size_t)k*272*256 + (size_t)(256+rr)*256 + col];
  }
}

// ---------------- CSR build (single block, deterministic) ----------------
__global__ void k_csr(const int* __restrict__ src, const int* __restrict__ dst){
  __shared__ int cnt[4096];
  __shared__ int png[4096];
  int t=threadIdx.x;
  for(int i=t;i<4096;i+=1024) cnt[i]=0;
  __syncthreads();
  for(int e=t;e<EE;e+=1024){
    atomicAdd(&cnt[dst[e]],1);
    atomicAdd(&cnt[2048+src[e]],1);
  }
  __syncthreads();
  for(int st=1;st<2048;st<<=1){
    for(int i=t;i<4096;i+=1024){
      int v=cnt[i];
      if((i&2047)>=st) v+=cnt[i-st];
      png[i]=v;
    }
    __syncthreads();
    for(int i=t;i<4096;i+=1024) cnt[i]=png[i];
    __syncthreads();
  }
  for(int i=t;i<4096;i+=1024){
    int dir=i>>11, n=i&2047;
    int ex = n? cnt[i-1]:0;
    d_offs[dir*(NN+1)+n]=ex;
    png[i]=ex;
    if(n==2047) d_offs[dir*(NN+1)+2048]=cnt[i];
  }
  __syncthreads();
  for(int e=t;e<EE;e+=1024){
    int p=atomicAdd(&png[dst[e]],1);       d_list[p]=e;
    int q=atomicAdd(&png[2048+src[e]],1);  d_list[EE+q]=e;
  }
  __syncthreads();
  for(int u=t;u<4096;u+=1024){
    int dir=u>>11, n=u&2047;
    int* list=d_list+dir*EE;
    int s=d_offs[dir*(NN+1)+n], e=d_offs[dir*(NN+1)+n+1];
    for(int i=s+1;i<e;i++){
      int v=list[i]; int j=i-1;
      while(j>=s && list[j]>v){ list[j+1]=list[j]; j--; }
      list[j+1]=v;
    }
    const int* other = dir? dst : src;
    for(int i=s;i<e;i++) d_gl[dir*EE+i]=other[list[i]];
  }
}

// ---------------- gather (on-the-fly edge-attr projection) / gru ----------------
__global__ void __launch_bounds__(256,4) k_gather(int p,
  const float* __restrict__ ea, const float* __restrict__ aggr_b){
  int n=blockIdx.x, d=threadIdx.x;
  int half=n>>11, node=n&2047;
  int k=p+2*half;
  __shared__ float sEB[16*256];
  __shared__ float sea[32*16];
  #pragma unroll
  for(int j=0;j<16;j++) sEB[j*256+d] = d_EB[j*1024 + k*256 + d];
  const int* offs=d_offs+p*(NN+1);
  const int* list=d_list+p*EE;
  const int* gl  =d_gl  +p*EE;
  int s=offs[node], e=offs[node+1];
  const float* hW = d_G1 + (size_t)half*2048*1024;
  float bias = aggr_b[k*256+d];
  float acc=0.f;
  __syncthreads();
  for(int i0=s; i0<e; i0+=32){
    int cnt = e-i0; if(cnt>32) cnt=32;
    for(int u=d; u<cnt*16; u+=256)
      sea[u] = ea[(size_t)list[i0+(u>>4)]*16 + (u&15)];
    __syncthreads();
    for(int q=0;q<cnt;q++){
      int o = gl[i0+q];
      float v = hW[(size_t)o*1024+d] + bias;
      #pragma unroll
      for(int j=0;j<16;j++) v = fmaf(sea[q*16+j], sEB[j*256+d], v);
      acc += fmaxf(v, 0.f);
    }
    __syncthreads();
  }
  __nv_bfloat16 hi=__float2bfloat16(acc);
  d_agghi[n*H2C+d]=hi;
  d_agglo[n*H2C+d]=__float2bfloat16(acc-__bfloat162float(hi));
}

__global__ void k_gru(){
  int n=blockIdx.x, d=threadIdx.x;
  const float* gi=d_gi+(size_t)n*G3C;
  const float* gh=d_G1+(size_t)n*1024+256;
  float ir=gi[d], iz=gi[H2C+d], inn=gi[2*H2C+d];
  float hr=gh[d], hz=gh[H2C+d], hn=gh[2*H2C+d];
  float r=1.f/(1.f+expf(-(ir+hr)));
  float z=1.f/(1.f+expf(-(iz+hz)));
  float nn=tanhf(inn + r*hn);
  float hv=d_h[n*H2C+d];
  float nv=(1.f-z)*nn + z*hv;
  d_h[n*H2C+d]=nv;
  __nv_bfloat16 hi=__float2bfloat16(nv);
  d_hhi[n*H2C+d]=hi;
  d_hlo[n*H2C+d]=__float2bfloat16(nv-__bfloat162float(hi));
}

// ---------------- pooling (3 kernels) ----------------
__global__ void k_poolscore(const float* __restrict__ pW1,
                            const float* __restrict__ pb1,
                            const float* __restrict__ pv){
  int p=blockIdx.y, x8=blockIdx.x, j=threadIdx.x;
  __shared__ float xs[8][DHH];
  int coff=(p<2)? 0 : DHH;
  #pragma unroll
  for(int q=0;q<8;q++){
    int x=x8*8+q;
    if(x<NN+8){
      bool isB = x>=NN;
      int node = isB? (SPECIAL + x - NN) : x;
      const float* hb = isB? (d_h + (size_t)2048*H2C) : d_h;
      xs[q][j]=hb[(size_t)node*H2C+coff+j];
    } else xs[q][j]=0.f;
  }
  __syncthreads();
  const float* W = pW1 + p*DHH*DHH;
  float bb = pb1[p*DHH+j];
  float acc[8];
  #pragma unroll
  for(int q=0;q<8;q++) acc[q]=bb;
  for(int d=0;d<DHH;d++){
    float w = W[d*DHH+j];
    #pragma unroll
    for(int q=0;q<8;q++) acc[q]=fmaf(xs[q][d], w, acc[q]);
  }
  float pvj = pv[p*DHH+j];
  #pragma unroll
  for(int q=0;q<8;q++){
    float y = tanhf(acc[q])*pvj;
    float s = blkSum<128>(y);
    if(j==0){
      int x=x8*8+q;
      if(x<NN) d_tA[p*NN+x]=s;
      else if(x<NN+8) d_tB[p*8+(x-NN)]=s;
    }
  }
}

__global__ void k_poolpart(){
  int c=blockIdx.x, p=blockIdx.y, t=threadIdx.x;
  float mx=-1e30f;
  for(int n=t;n<NN;n+=128) mx=fmaxf(mx, d_tA[p*NN+n]);
  if(t<8) mx=fmaxf(mx, d_tB[p*8+t]);
  float M = blkMax<128>(mx);
  if(c==0 && t==0) d_Mx[p]=M;
  int n0=c*128;
  int lim = SPECIAL - n0; if(lim>128) lim=128; if(lim<0) lim=0;
  int coff=(p<2)? 0 : DHH;
  __shared__ float ws[128];
  float w = (t<lim)? expf(d_tA[p*NN+n0+t]-M) : 0.f;
  ws[t]=w;
  float den = blkSum<128>(w);
  float num=0.f;
  for(int i=0;i<lim;i++)
    num = fmaf(ws[i], d_h[(size_t)(n0+i)*H2C+coff+t], num);
  d_pNum[(p*16+c)*DHH+t]=num;
  if(t==0) d_pDen[p*16+c]=den;
}

__global__ void k_poolstates(){
  int s=blockIdx.x, p=blockIdx.y, d=threadIdx.x;
  int coff=(p<2)? 0 : DHH;
  float M=d_Mx[p];
  float num=0.f, den=0.f;
  #pragma unroll
  for(int c=0;c<16;c++){
    num += d_pNum[(p*16+c)*DHH+d];
    den += d_pDen[p*16+c];
  }
  #pragma unroll
  for(int j=0;j<8;j++){
    int node=SPECIAL+j;
    int bit=(s>>(7-j))&1;
    float tv = bit? d_tB[p*8+j] : d_tA[p*NN+node];
    float w = expf(tv-M);
    const float* h = bit? (d_h+(size_t)2048*H2C) : d_h;
    num = fmaf(w, h[(size_t)node*H2C+coff+d], num);
    den += w;
  }
  d_pooled[(p*SS+s)*DHH + d] = num/den;
}

// ---------------- outputs ----------------
__global__ void k_out(const float* __restrict__ finite,
                      const float* __restrict__ trans,
                      float* __restrict__ out){
  int a=blockIdx.x, b=threadIdx.x;
  int idx=a*256+b;
  out[idx]=d_ho[idx];
  out[65536+idx]= (finite[idx]>0.f)?1.f:0.f;
  out[3*65536+idx]=trans[idx];
  float x=d_ho[65536+idx];
  float M=blkMax<256>(x);
  float e=expf(x-M);
  float sum=blkSum<256>(e);
  out[2*65536 + idx] = x - M - logf(sum);
}

// ---------------- host ----------------
static float* symf(const void* s){ void* p=nullptr; cudaGetSymbolAddress(&p, s); return (float*)p; }
static __nv_bfloat16* symb(const void* s){ void* p=nullptr; cudaGetSymbolAddress(&p, s); return (__nv_bfloat16*)p; }

extern "C" void kernel_launch(void* const* d_in, const int* in_sizes, int n_in,
                              void* d_out, int out_size){
  const int*   edge_index=(const int*)d_in[0];
  const float* edge_attr =(const float*)d_in[1];
  const float* h_init0   =(const float*)d_in[2];
  const float* h_init1   =(const float*)d_in[3];
  const float* finite    =(const float*)d_in[4];
  const float* trans     =(const float*)d_in[5];
  const float* init_W    =(const float*)d_in[6];
  const float* init_b    =(const float*)d_in[7];
  const float* aggr_W    =(const float*)d_in[8];
  const float* aggr_b    =(const float*)d_in[9];
  const float* gWih      =(const float*)d_in[10];
  const float* gWhh      =(const float*)d_in[11];
  const float* gbih      =(const float*)d_in[12];
  const float* gbhh      =(const float*)d_in[13];
  const float* pW1       =(const float*)d_in[14];
  const float* pb1       =(const float*)d_in[15];
  const float* pv        =(const float*)d_in[16];
  const float* rW1       =(const float*)d_in[17];
  const float* rb1       =(const float*)d_in[18];
  const float* rg1       =(const float*)d_in[19];
  const float* rbe1      =(const float*)d_in[20];
  const float* rW2       =(const float*)d_in[21];
  const float* rb2       =(const float*)d_in[22];
  const float* rg2       =(const float*)d_in[23];
  const float* rbe2      =(const float*)d_in[24];
  const float* rW3       =(const float*)d_in[25];
  const float* rb3       =(const float*)d_in[26];
  const int* src=edge_index;
  const int* dst=edge_index+EE;
  float* out=(float*)d_out;

  float* P_bias1= symf(d_bias1);
  float* P_G1   = symf(d_G1);
  float* P_gi   = symf(d_gi);
  __nv_bfloat16* P_hhi  = symb(d_hhi);
  __nv_bfloat16* P_hlo  = symb(d_hlo);
  __nv_bfloat16* P_ahi  = symb(d_agghi);
  __nv_bfloat16* P_alo  = symb(d_agglo);
  __nv_bfloat16* P_B1h  = symb(d_B1t_hi);
  __nv_bfloat16* P_B1l  = symb(d_B1t_lo);
  __nv_bfloat16* P_B2h  = symb(d_B2t_hi);
  __nv_bfloat16* P_B2l  = symb(d_B2t_lo);

  cudaFuncSetAttribute(hmma, cudaFuncAttributeMaxDynamicSharedMemorySize, HSMEM);
  cudaFuncSetAttribute(k_ro, cudaFuncAttributeMaxDynamicSharedMemorySize, ROSMEM);

  // prep
  k_packAll<<<7762,256>>>(aggr_W, gWhh, gbhh, gWih, rW2);
  k_csr<<<1,1024>>>(src,dst);
  k_init<<<dim3(4,32,2),256>>>(h_init0, h_init1, init_W, init_b);

  // message passing
  for(int r=0;r<4;r++){
    for(int p=0;p<2;p++){
      hmma<<<dim3(8,32),256,HSMEM>>>(2048,
        P_hhi, P_hlo,
        P_B1h+(size_t)p*262144, P_B1l+(size_t)p*262144,
        P_B1h+(size_t)(p+2)*262144, P_B1l+(size_t)(p+2)*262144,
        P_bias1+p*1024, P_bias1+(p+2)*1024, P_G1, 1024);
      k_gather<<<NB,256>>>(p, edge_attr, aggr_b);
      hmma<<<dim3(6,32),256,HSMEM>>>(2048,
        P_ahi, P_alo,
        P_B2h+(size_t)p*196608, P_B2l+(size_t)p*196608,
        P_B2h+(size_t)(p+2)*196608, P_B2l+(size_t)(p+2)*196608,
        gbih+p*G3C, gbih+(p+2)*G3C, P_gi, G3C);
      k_gru<<<NB,256>>>();
    }
  }

  // pooling (3 kernels)
  k_poolscore<<<dim3(257,4),128>>>(pW1,pb1,pv);
  k_poolpart<<<dim3(16,4),128>>>();
  k_poolstates<<<dim3(SS,4),128>>>();

  // readout
  k_qi<<<dim3(4,4,4),256>>>(rW1);
  k_ro<<<dim3(1024,2),256,ROSMEM>>>(rb1,rg1,rbe1,rb2,rg2,rbe2,rW3,rb3);

  // outputs
  k_out<<<SS,256>>>(finite,trans,out);
}

// round 16
// speedup vs baseline: 1.1749x; 1.0238x over previous
#include <cuda_runtime.h>
#include <cuda_bf16.h>
#include <cstdint>
#include <math.h>

#define NN 2048
#define EE 16384
#define SS 256
#define DHH 128
#define H2C 256
#define DMC 256
#define G3C 768
#define SPECIAL 2040
#define NB 4096

// ---------------- device scratch ----------------
__device__ __align__(256) float d_h[NB*H2C];
__device__ __align__(256) float d_EB[16*1024];
__device__ __align__(256) float d_bias1[4*1024];
__device__ __align__(256) float d_G1[NB*1024];
__device__ __align__(256) float d_gi[NB*G3C];
__device__ __align__(256) __nv_bfloat16 d_hhi[NB*H2C];
__device__ __align__(256) __nv_bfloat16 d_hlo[NB*H2C];
__device__ __align__(256) __nv_bfloat16 d_agghi[NB*H2C];
__device__ __align__(256) __nv_bfloat16 d_agglo[NB*H2C];
__device__ __align__(256) __nv_bfloat16 d_B1t_hi[4*1024*256];
__device__ __align__(256) __nv_bfloat16 d_B1t_lo[4*1024*256];
__device__ __align__(256) __nv_bfloat16 d_B2t_hi[4*768*256];
__device__ __align__(256) __nv_bfloat16 d_B2t_lo[4*768*256];
__device__ __align__(256) __nv_bfloat16 d_W2t_hi[2*256*256];
__device__ __align__(256) __nv_bfloat16 d_W2t_lo[2*256*256];
__device__ int   d_offs[2*(NN+1)];
__device__ int   d_list[2*EE];
__device__ int   d_gl[2*EE];
__device__ float d_tA[4*NN];
__device__ float d_tB[4*8];
__device__ float d_Mx[4];
__device__ float d_pNum[4*16*DHH];
__device__ float d_pDen[4*16];
__device__ __align__(256) float d_pooled[4*SS*DHH];
__device__ __align__(256) float d_QI[4*SS*DMC];
__device__ float d_ho[2*SS*SS];

// ---------------- helpers ----------------
__device__ __forceinline__ uint32_t smem_u32(const void* p){
  uint32_t a; asm("{ .reg .u64 t; cvta.to.shared.u64 t, %1; cvt.u32.u64 %0, t; }" : "=r"(a) : "l"(p)); return a;
}
__device__ __forceinline__ void mma16816(float* c, const uint32_t* a, const uint32_t* b){
  asm volatile(
    "mma.sync.aligned.m16n8k16.row.col.f32.bf16.bf16.f32 "
    "{%0,%1,%2,%3}, {%4,%5,%6,%7}, {%8,%9}, {%0,%1,%2,%3};"
    : "+f"(c[0]), "+f"(c[1]), "+f"(c[2]), "+f"(c[3])
    : "r"(a[0]), "r"(a[1]), "r"(a[2]), "r"(a[3]), "r"(b[0]), "r"(b[1]));
}
__device__ __forceinline__ void ldmx4(uint32_t* r, uint32_t addr){
  asm volatile("ldmatrix.sync.aligned.m8n8.x4.shared.b16 {%0,%1,%2,%3}, [%4];"
    : "=r"(r[0]), "=r"(r[1]), "=r"(r[2]), "=r"(r[3]) : "r"(addr));
}

// ---------------- split-bf16 HMMA GEMM: 64x64 tile, 128 thr, 4 warps ----------------
// Higher occupancy (6 CTAs/SM = 24 warps) to fill the tensor pipe.
// Per-acc accumulation order identical to previous 128x128 version
// (chunk -> ks -> hi*hi, hi*lo, lo*hi) => bitwise-identical results.
#define HSMEM 32768
__device__ __forceinline__ void h_load64(int tid, uint32_t base,
  const __nv_bfloat16* Ahi, const __nv_bfloat16* Alo,
  const __nv_bfloat16* Bhi, const __nv_bfloat16* Blo,
  int m0, int n0, int c)
{
  const __nv_bfloat16* srcs[4] = { Ahi, Alo, Bhi, Blo };
  int rows0[4] = { m0, m0, n0, n0 };
  #pragma unroll
  for(int a=0;a<4;a++){
    const __nv_bfloat16* S = srcs[a];
    uint32_t dbase = base + a*4096u;
    int row0 = rows0[a];
    #pragma unroll
    for(int i=0;i<2;i++){
      int u = tid + i*128;
      int r = u>>2, col = u&3;
      const void* src = S + (size_t)(row0+r)*256 + c*32 + col*8;
      uint32_t dst = dbase + (uint32_t)(r*64) + (uint32_t)((col ^ ((r>>1)&3))<<4);
      asm volatile("cp.async.cg.shared.global [%0], [%1], 16;" :: "r"(dst), "l"(src));
    }
  }
  asm volatile("cp.async.commit_group;");
}

__global__ void __launch_bounds__(128,6) hmma(int Msplit,
  const __nv_bfloat16* __restrict__ Ahi, const __nv_bfloat16* __restrict__ Alo,
  const __nv_bfloat16* __restrict__ Bhi0, const __nv_bfloat16* __restrict__ Blo0,
  const __nv_bfloat16* __restrict__ Bhi1, const __nv_bfloat16* __restrict__ Blo1,
  const float* __restrict__ bias0, const float* __restrict__ bias1,
  float* __restrict__ C, int ldc)
{
  extern __shared__ char smem[];
  uint32_t sb = smem_u32(smem);
  int tid=threadIdx.x, lane=tid&31, wid=tid>>5;
  int m0=blockIdx.y*64, n0=blockIdx.x*64;
  const __nv_bfloat16* Bhi=(m0<Msplit)?Bhi0:Bhi1;
  const __nv_bfloat16* Blo=(m0<Msplit)?Blo0:Blo1;
  const float* bias=(m0<Msplit)?bias0:bias1;
  int wm = wid>>1, wn = wid&1;          // 2x2 warps, warp tile 32x32

  float acc[2][4][4];
  #pragma unroll
  for(int i=0;i<2;i++)
    #pragma unroll
    for(int j=0;j<4;j++)
      #pragma unroll
      for(int k=0;k<4;k++) acc[i][j][k]=0.f;

  h_load64(tid, sb, Ahi, Alo, Bhi, Blo, m0, n0, 0);

  for(int c=0;c<8;c++){
    uint32_t buf = sb + (uint32_t)(c&1)*16384u;
    asm volatile("cp.async.wait_group 0;");
    __syncthreads();
    if(c<7)
      h_load64(tid, sb + (uint32_t)((c+1)&1)*16384u, Ahi, Alo, Bhi, Blo, m0, n0, c+1);

    uint32_t aHB=buf, aLB=buf+4096u, bHB=buf+8192u, bLB=buf+12288u;
    #pragma unroll
    for(int ks=0; ks<2; ks++){
      uint32_t bh[4][2], bl[4][2];
      {
        int rn = wn*32 + ((lane>>4)<<3) + (lane&7);
        int cB = 2*ks + ((lane>>3)&1);
        #pragma unroll
        for(int nip=0; nip<2; nip++){
          int r = rn + nip*16;
          uint32_t off = (uint32_t)(r*64) + (uint32_t)((cB ^ ((r>>1)&3))<<4);
          uint32_t t[4];
          ldmx4(t, bHB + off);
          bh[2*nip][0]=t[0]; bh[2*nip][1]=t[1]; bh[2*nip+1][0]=t[2]; bh[2*nip+1][1]=t[3];
          ldmx4(t, bLB + off);
          bl[2*nip][0]=t[0]; bl[2*nip][1]=t[1]; bl[2*nip+1][0]=t[2]; bl[2*nip+1][1]=t[3];
        }
      }
      uint32_t af[2][4];
      int rA = lane&15, cA = 2*ks + (lane>>4);
      #pragma unroll
      for(int mi=0;mi<2;mi++){
        int r = wm*32 + mi*16 + rA;
        uint32_t off = (uint32_t)(r*64) + (uint32_t)((cA ^ ((r>>1)&3))<<4);
        ldmx4(af[mi], aHB + off);
      }
      #pragma unroll
      for(int mi=0;mi<2;mi++)
        #pragma unroll
        for(int ni=0;ni<4;ni++)
          mma16816(acc[mi][ni], af[mi], bh[ni]);   // hi*hi
      #pragma unroll
      for(int mi=0;mi<2;mi++)
        #pragma unroll
        for(int ni=0;ni<4;ni++)
          mma16816(acc[mi][ni], af[mi], bl[ni]);   // hi*lo
      #pragma unroll
      for(int mi=0;mi<2;mi++){
        int r = wm*32 + mi*16 + rA;
        uint32_t off = (uint32_t)(r*64) + (uint32_t)((cA ^ ((r>>1)&3))<<4);
        ldmx4(af[mi], aLB + off);
      }
      #pragma unroll
      for(int mi=0;mi<2;mi++)
        #pragma unroll
        for(int ni=0;ni<4;ni++)
          mma16816(acc[mi][ni], af[mi], bh[ni]);   // lo*hi
    }
  }

  int gr = lane>>2, gc = (lane&3)*2;
  #pragma unroll
  for(int mi=0;mi<2;mi++){
    int r1 = m0 + wm*32 + mi*16 + gr;
    #pragma unroll
    for(int ni=0;ni<4;ni++){
      int col = n0 + wn*32 + ni*8 + gc;
      float b0 = bias[col], b1 = bias[col+1];
      float2 v0 = make_float2(acc[mi][ni][0]+b0, acc[mi][ni][1]+b1);
      float2 v1 = make_float2(acc[mi][ni][2]+b0, acc[mi][ni][3]+b1);
      *(float2*)(C + (size_t)r1*ldc + col) = v0;
      *(float2*)(C + (size_t)(r1+8)*ldc + col) = v1;
    }
  }
}

// ---------------- fused readout (96KB smem -> 2 CTAs/SM) ----------------
#define ROSMEM 98304
__global__ void __launch_bounds__(256,2) k_ro(
  const float* __restrict__ rb1, const float* __restrict__ rg1, const float* __restrict__ rbe1,
  const float* __restrict__ rb2, const float* __restrict__ rg2, const float* __restrict__ rbe2,
  const float* __restrict__ rW3, const float* __restrict__ rb3)
{
  extern __shared__ char smem[];
  uint32_t sb = smem_u32(smem);
  int h = blockIdx.y;
  int tid=threadIdx.x, lane=tid&31, wid=tid>>5;
  int wm=wid>>2, wn=wid&3;
  int row0 = blockIdx.x*64;

  const float* Q1 = d_QI + (size_t)(2*h)*65536;
  const float* I1 = d_QI + (size_t)(2*h+1)*65536;
  const float* b1 = rb1 + h*256;
  const float* g1 = rg1 + h*256;
  const float* be1 = rbe1 + h*256;
  const __nv_bfloat16* Wh = d_W2t_hi + (size_t)h*65536;
  const __nv_bfloat16* Wl = d_W2t_lo + (size_t)h*65536;

  #define RO_BLOAD(cc) do{ \
    uint32_t base_ = sb + 65536u; \
    _Pragma("unroll") \
    for(int i_=0;i_<4;i_++){ \
      int u_ = tid + i_*256; int r_=u_>>2, col_=u_&3; \
      const void* sh_ = Wh + (size_t)r_*256 + (cc)*32 + col_*8; \
      const void* sl_ = Wl + (size_t)r_*256 + (cc)*32 + col_*8; \
      uint32_t d_ = base_ + (uint32_t)(r_*64) + (uint32_t)((col_ ^ ((r_>>1)&3))<<4); \
      asm volatile("cp.async.cg.shared.global [%0], [%1], 16;" :: "r"(d_), "l"(sh_)); \
      asm volatile("cp.async.cg.shared.global [%0], [%1], 16;" :: "r"(d_+16384u), "l"(sl_)); \
    } \
    asm volatile("cp.async.commit_group;"); \
  }while(0)

  RO_BLOAD(0);

  {
    int rl = tid>>2, cg = tid&3;
    int grow = row0 + rl;
    int a = grow>>8, b = grow&255;
    const float* qrow = Q1 + (size_t)b*256 + cg*64;
    const float* irow = I1 + (size_t)a*256 + cg*64;
    const float* brow = b1 + cg*64;
    float s1=0.f, s2=0.f;
    #pragma unroll 8
    for(int i=0;i<64;i++){
      float z = qrow[i]+irow[i]+brow[i];
      s1+=z; s2+=z*z;
    }
    s1 += __shfl_xor_sync(0xffffffffu,s1,1); s2 += __shfl_xor_sync(0xffffffffu,s2,1);
    s1 += __shfl_xor_sync(0xffffffffu,s1,2); s2 += __shfl_xor_sync(0xffffffffu,s2,2);
    float mean = s1*(1.f/256.f);
    float rstd = rsqrtf(s2*(1.f/256.f)-mean*mean+1e-5f);
    const float* g1c = g1 + cg*64;
    const float* be1c = be1 + cg*64;
    #pragma unroll
    for(int g=0; g<8; g++){
      uint32_t hi4[4], lo4[4];
      #pragma unroll
      for(int ii=0; ii<4; ii++){
        int j = g*8 + 2*ii;
        float z0 = qrow[j]+irow[j]+brow[j];
        float z1 = qrow[j+1]+irow[j+1]+brow[j+1];
        float v0 = fmaxf((z0-mean)*rstd*g1c[j]+be1c[j], 0.f);
        float v1 = fmaxf((z1-mean)*rstd*g1c[j+1]+be1c[j+1], 0.f);
        __nv_bfloat16 h0=__float2bfloat16(v0), h1=__float2bfloat16(v1);
        __nv_bfloat16 l0=__float2bfloat16(v0-__bfloat162float(h0));
        __nv_bfloat16 l1=__float2bfloat16(v1-__bfloat162float(h1));
        hi4[ii] = ((uint32_t)__bfloat16_as_ushort(h1)<<16) | (uint32_t)__bfloat16_as_ushort(h0);
        lo4[ii] = ((uint32_t)__bfloat16_as_ushort(l1)<<16) | (uint32_t)__bfloat16_as_ushort(l0);
      }
      int c16 = cg*8+g;
      uint32_t off = (uint32_t)(rl*512) + (uint32_t)((c16 ^ (rl&7))<<4);
      *(uint4*)(smem + off) = make_uint4(hi4[0],hi4[1],hi4[2],hi4[3]);
      *(uint4*)(smem + 32768 + off) = make_uint4(lo4[0],lo4[1],lo4[2],lo4[3]);
    }
  }
  __syncthreads();

  float acc[2][8][4];
  #pragma unroll
  for(int i=0;i<2;i++)
    #pragma unroll
    for(int j=0;j<8;j++)
      #pragma unroll
      for(int k=0;k<4;k++) acc[i][j][k]=0.f;

  for(int c=0;c<8;c++){
    asm volatile("cp.async.wait_group 0;");
    __syncthreads();
    uint32_t bB = sb + 65536u;
    #pragma unroll
    for(int ks=0;ks<2;ks++){
      uint32_t ahi[2][4], alo[2][4];
      int rA = lane&15;
      int c16 = c*4 + ks*2 + (lane>>4);
      #pragma unroll
      for(int mi=0;mi<2;mi++){
        int row = wm*32 + mi*16 + rA;
        uint32_t off = (uint32_t)(row*512) + (uint32_t)((c16 ^ (row&7))<<4);
        ldmx4(ahi[mi], sb + off);
        ldmx4(alo[mi], sb + 32768u + off);
      }
      uint32_t bh[8][2], bl[8][2];
      int rn = wn*64 + ((lane>>4)<<3) + (lane&7);
      int cB = 2*ks + ((lane>>3)&1);
      #pragma unroll
      for(int nip=0;nip<4;nip++){
        int r = rn + nip*16;
        uint32_t off = (uint32_t)(r*64) + (uint32_t)((cB ^ ((r>>1)&3))<<4);
        uint32_t t[4];
        ldmx4(t, bB + off);
        bh[2*nip][0]=t[0]; bh[2*nip][1]=t[1]; bh[2*nip+1][0]=t[2]; bh[2*nip+1][1]=t[3];
        ldmx4(t, bB + 16384u + off);
        bl[2*nip][0]=t[0]; bl[2*nip][1]=t[1]; bl[2*nip+1][0]=t[2]; bl[2*nip+1][1]=t[3];
      }
      #pragma unroll
      for(int mi=0;mi<2;mi++)
        #pragma unroll
        for(int ni=0;ni<8;ni++)
          mma16816(acc[mi][ni], ahi[mi], bh[ni]);
      #pragma unroll
      for(int mi=0;mi<2;mi++)
        #pragma unroll
        for(int ni=0;ni<8;ni++)
          mma16816(acc[mi][ni], ahi[mi], bl[ni]);
      #pragma unroll
      for(int mi=0;mi<2;mi++)
        #pragma unroll
        for(int ni=0;ni<8;ni++)
          mma16816(acc[mi][ni], alo[mi], bh[ni]);
    }
    __syncthreads();
    if(c<7) RO_BLOAD(c+1);
  }

  const float* b2 = rb2 + h*256;
  const float* g2 = rg2 + h*256;
  const float* be2 = rbe2 + h*256;
  const float* W3 = rW3 + h*256;
  float* ps = (float*)smem;
  float* pq = ps + 256;
  float* pd = pq + 256;
  float* mn2 = pd + 256;
  float* rs2 = mn2 + 64;
  int gr=lane>>2, gc=(lane&3)*2;
  #pragma unroll
  for(int mi=0;mi<2;mi++){
    #pragma unroll
    for(int half=0;half<2;half++){
      float s=0.f,q=0.f;
      #pragma unroll
      for(int ni=0;ni<8;ni++){
        int col = wn*64 + ni*8 + gc;
        float y0 = acc[mi][ni][half*2+0] + b2[col];
        float y1 = acc[mi][ni][half*2+1] + b2[col+1];
        s += y0+y1; q += y0*y0+y1*y1;
      }
      s += __shfl_xor_sync(0xffffffffu,s,1); q += __shfl_xor_sync(0xffffffffu,q,1);
      s += __shfl_xor_sync(0xffffffffu,s,2); q += __shfl_xor_sync(0xffffffffu,q,2);
      if((lane&3)==0){
        int rl2 = wm*32+mi*16+half*8+gr;
        ps[rl2*4+wn]=s; pq[rl2*4+wn]=q;
      }
    }
  }
  __syncthreads();
  if(tid<64){
    float s=ps[tid*4]+ps[tid*4+1]+ps[tid*4+2]+ps[tid*4+3];
    float q=pq[tid*4]+pq[tid*4+1]+pq[tid*4+2]+pq[tid*4+3];
    float m=s*(1.f/256.f);
    mn2[tid]=m; rs2[tid]=rsqrtf(q*(1.f/256.f)-m*m+1e-5f);
  }
  __syncthreads();
  #pragma unroll
  for(int mi=0;mi<2;mi++){
    #pragma unroll
    for(int half=0;half<2;half++){
      int rl2 = wm*32+mi*16+half*8+gr;
      float m=mn2[rl2], rs=rs2[rl2];
      float dsum=0.f;
      #pragma unroll
      for(int ni=0;ni<8;ni++){
        int col = wn*64 + ni*8 + gc;
        float y0 = acc[mi][ni][half*2+0] + b2[col];
        float y1 = acc[mi][ni][half*2+1] + b2[col+1];
        float u0 = fmaxf((y0-m)*rs*g2[col]+be2[col], 0.f);
        float u1 = fmaxf((y1-m)*rs*g2[col+1]+be2[col+1], 0.f);
        dsum += u0*W3[col] + u1*W3[col+1];
      }
      dsum += __shfl_xor_sync(0xffffffffu,dsum,1);
      dsum += __shfl_xor_sync(0xffffffffu,dsum,2);
      if((lane&3)==0) pd[rl2*4+wn]=dsum;
    }
  }
  __syncthreads();
  if(tid<64)
    d_ho[(size_t)h*65536 + row0 + tid] =
      pd[tid*4]+pd[tid*4+1]+pd[tid*4+2]+pd[tid*4+3] + rb3[h];
}

// ---------------- block reductions ----------------
template<int NT>
__device__ __forceinline__ float blkSum(float v){
  __shared__ float sh[NT/32];
  __shared__ float tot;
  int lane=threadIdx.x&31, w=threadIdx.x>>5;
  #pragma unroll
  for(int o=16;o>0;o>>=1) v+=__shfl_down_sync(0xffffffffu,v,o);
  if(lane==0) sh[w]=v;
  __syncthreads();
  if(w==0){
    float x=(lane<NT/32)? sh[lane] : 0.f;
    #pragma unroll
    for(int o=(NT/32)/2;o>0;o>>=1) x+=__shfl_down_sync(0xffffffffu,x,o);
    if(lane==0) tot=x;
  }
  __syncthreads();
  return tot;
}
template<int NT>
__device__ __forceinline__ float blkMax(float v){
  __shared__ float sh[NT/32];
  __shared__ float tot;
  int lane=threadIdx.x&31, w=threadIdx.x>>5;
  #pragma unroll
  for(int o=16;o>0;o>>=1) v=fmaxf(v,__shfl_down_sync(0xffffffffu,v,o));
  if(lane==0) sh[w]=v;
  __syncthreads();
  if(w==0){
    float x=(lane<NT/32)? sh[lane] : -1e30f;
    #pragma unroll
    for(int o=(NT/32)/2;o>0;o>>=1) x=fmaxf(x,__shfl_down_sync(0xffffffffu,x,o));
    if(lane==0) tot=x;
  }
  __syncthreads();
  return tot;
}

// ---------------- small fp32 GEMM body (64x64 tiles, K=128) ----------------
__device__ __forceinline__ void sgemm64(
  const float* __restrict__ A,int lda,const float* __restrict__ B,int ldb,
  const float* __restrict__ bias, float* __restrict__ C,int ldc,
  __nv_bfloat16* Chi, __nv_bfloat16* Clo, int m0, int n0)
{
  __shared__ float As[16][64];
  __shared__ float Bs[16][64];
  int tid=threadIdx.x;
  int tr=(tid>>4)*4, tc=(tid&15)*4;
  int aRow=tid>>2, aCol=(tid&3)*4;
  int bRow=tid>>4, bCol=(tid&15)*4;
  float acc[4][4];
  #pragma unroll
  for(int i=0;i<4;i++)
    #pragma unroll
    for(int j=0;j<4;j++) acc[i][j]=0.f;
  for(int k0=0;k0<128;k0+=16){
    float4 av=*(const float4*)(A+(size_t)(m0+aRow)*lda+k0+aCol);
    As[aCol+0][aRow]=av.x; As[aCol+1][aRow]=av.y;
    As[aCol+2][aRow]=av.z; As[aCol+3][aRow]=av.w;
    float4 bv=*(const float4*)(B+(size_t)(k0+bRow)*ldb+n0+bCol);
    *(float4*)(&Bs[bRow][bCol])=bv;
    __syncthreads();
    #pragma unroll
    for(int kk=0;kk<16;kk++){
      float af[4], bf[4];
      #pragma unroll
      for(int i=0;i<4;i++) af[i]=As[kk][tr+i];
      #pragma unroll
      for(int j=0;j<4;j++) bf[j]=Bs[kk][tc+j];
      #pragma unroll
      for(int i=0;i<4;i++)
        #pragma unroll
        for(int j=0;j<4;j++) acc[i][j]=fmaf(af[i],bf[j],acc[i][j]);
    }
    __syncthreads();
  }
  #pragma unroll
  for(int i=0;i<4;i++){
    size_t rowoff=(size_t)(m0+tr+i)*ldc + n0+tc;
    #pragma unroll
    for(int j=0;j<4;j++){
      float v=acc[i][j];
      if(bias) v+=bias[n0+tc+j];
      C[rowoff+j]=v;
      if(Chi){
        __nv_bfloat16 hi=__float2bfloat16(v);
        Chi[rowoff+j]=hi;
        Clo[rowoff+j]=__float2bfloat16(v-__bfloat162float(hi));
      }
    }
  }
}

__global__ void __launch_bounds__(256,4) k_init(
  const float* __restrict__ h_init0, const float* __restrict__ h_init1,
  const float* __restrict__ init_W, const float* __restrict__ init_b)
{
  int z=blockIdx.z;
  sgemm64(z? h_init0 : h_init1, 128,
           init_W+(size_t)z*128*256, 256, init_b+z*256,
           d_h+(size_t)z*2048*256, 256,
           d_hhi+(size_t)z*2048*256, d_hlo+(size_t)z*2048*256,
           blockIdx.y*64, blockIdx.x*64);
}

__global__ void __launch_bounds__(256,4) k_qi(const float* __restrict__ rW1){
  int z=blockIdx.z;
  sgemm64(d_pooled+(size_t)z*SS*DHH, 128,
           rW1+(size_t)(z>>1)*65536+(size_t)(z&1)*128*256, 256, nullptr,
           d_QI+(size_t)z*65536, 256, nullptr, nullptr,
           blockIdx.y*64, blockIdx.x*64);
}

// ---------------- pack all weights ----------------
__global__ void k_packAll(const float* __restrict__ aggr_W,
                          const float* __restrict__ gWhh,
                          const float* __restrict__ gbhh,
                          const float* __restrict__ gWih,
                          const float* __restrict__ rW2){
  long idx=(long)blockIdx.x*256+threadIdx.x;
  if(idx<4096){
    int k=(int)(idx>>10), c=(int)(idx&1023);
    d_bias1[idx] = (c<256)? 0.f : gbhh[k*768 + (c-256)];
  } else if(idx<4096+1048576){
    long r=idx-4096;
    int k=(int)(r>>18);
    int rem=(int)(r&262143);
    int n=rem>>8, kk=rem&255;
    float v = (n<256)? aggr_W[(size_t)k*272*256 + (size_t)kk*256 + n]
                     : gWhh[(size_t)k*768*256 + (size_t)(n-256)*256 + kk];
    __nv_bfloat16 hi=__float2bfloat16(v);
    d_B1t_hi[r]=hi; d_B1t_lo[r]=__float2bfloat16(v-__bfloat162float(hi));
  } else if(idx<4096+1048576+786432){
    long r=idx-4096-1048576;
    float v=gWih[r];
    __nv_bfloat16 hi=__float2bfloat16(v);
    d_B2t_hi[r]=hi; d_B2t_lo[r]=__float2bfloat16(v-__bfloat162float(hi));
  } else if(idx<4096+1048576+786432+131072){
    long r=idx-4096-1048576-786432;
    int h=(int)(r>>16); int rem=(int)(r&65535);
    int n=rem>>8, kk=rem&255;
    float v=rW2[(size_t)h*65536 + (size_t)kk*256 + n];
    __nv_bfloat16 hi=__float2bfloat16(v);
    d_W2t_hi[r]=hi; d_W2t_lo[r]=__float2bfloat16(v-__bfloat162float(hi));
  } else if(idx<4096+1048576+786432+131072+16384){
    long r=idx-4096-1048576-786432-131072;
    int rr=(int)(r>>10), c=(int)(r&1023);
    int k=c>>8, col=c&255;
    d_EB[r]=aggr_W[(size_t)k*272*256 + (size_t)(256+rr)*256 + col];
  }
}

// ---------------- CSR build (single block, deterministic) ----------------
__global__ void k_csr(const int* __restrict__ src, const int* __restrict__ dst){
  __shared__ int cnt[4096];
  __shared__ int png[4096];
  int t=threadIdx.x;
  for(int i=t;i<4096;i+=1024) cnt[i]=0;
  __syncthreads();
  for(int e=t;e<EE;e+=1024){
    atomicAdd(&cnt[dst[e]],1);
    atomicAdd(&cnt[2048+src[e]],1);
  }
  __syncthreads();
  for(int st=1;st<2048;st<<=1){
    for(int i=t;i<4096;i+=1024){
      int v=cnt[i];
      if((i&2047)>=st) v+=cnt[i-st];
      png[i]=v;
    }
    __syncthreads();
    for(int i=t;i<4096;i+=1024) cnt[i]=png[i];
    __syncthreads();
  }
  for(int i=t;i<4096;i+=1024){
    int dir=i>>11, n=i&2047;
    int ex = n? cnt[i-1]:0;
    d_offs[dir*(NN+1)+n]=ex;
    png[i]=ex;
    if(n==2047) d_offs[dir*(NN+1)+2048]=cnt[i];
  }
  __syncthreads();
  for(int e=t;e<EE;e+=1024){
    int p=atomicAdd(&png[dst[e]],1);       d_list[p]=e;
    int q=atomicAdd(&png[2048+src[e]],1);  d_list[EE+q]=e;
  }
  __syncthreads();
  for(int u=t;u<4096;u+=1024){
    int dir=u>>11, n=u&2047;
    int* list=d_list+dir*EE;
    int s=d_offs[dir*(NN+1)+n], e=d_offs[dir*(NN+1)+n+1];
    for(int i=s+1;i<e;i++){
      int v=list[i]; int j=i-1;
      while(j>=s && list[j]>v){ list[j+1]=list[j]; j--; }
      list[j+1]=v;
    }
    const int* other = dir? dst : src;
    for(int i=s;i<e;i++) d_gl[dir*EE+i]=other[list[i]];
  }
}

// ---------------- gather (on-the-fly edge-attr projection) / gru ----------------
__global__ void __launch_bounds__(256,4) k_gather(int p,
  const float* __restrict__ ea, const float* __restrict__ aggr_b){
  int n=blockIdx.x, d=threadIdx.x;
  int half=n>>11, node=n&2047;
  int k=p+2*half;
  __shared__ float sEB[16*256];
  __shared__ float sea[32*16];
  #pragma unroll
  for(int j=0;j<16;j++) sEB[j*256+d] = d_EB[j*1024 + k*256 + d];
  const int* offs=d_offs+p*(NN+1);
  const int* list=d_list+p*EE;
  const int* gl  =d_gl  +p*EE;
  int s=offs[node], e=offs[node+1];
  const float* hW = d_G1 + (size_t)half*2048*1024;
  float bias = aggr_b[k*256+d];
  float acc=0.f;
  __syncthreads();
  for(int i0=s; i0<e; i0+=32){
    int cnt = e-i0; if(cnt>32) cnt=32;
    for(int u=d; u<cnt*16; u+=256)
      sea[u] = ea[(size_t)list[i0+(u>>4)]*16 + (u&15)];
    __syncthreads();
    for(int q=0;q<cnt;q++){
      int o = gl[i0+q];
      float v = hW[(size_t)o*1024+d] + bias;
      #pragma unroll
      for(int j=0;j<16;j++) v = fmaf(sea[q*16+j], sEB[j*256+d], v);
      acc += fmaxf(v, 0.f);
    }
    __syncthreads();
  }
  __nv_bfloat16 hi=__float2bfloat16(acc);
  d_agghi[n*H2C+d]=hi;
  d_agglo[n*H2C+d]=__float2bfloat16(acc-__bfloat162float(hi));
}

__global__ void k_gru(){
  int n=blockIdx.x, d=threadIdx.x;
  const float* gi=d_gi+(size_t)n*G3C;
  const float* gh=d_G1+(size_t)n*1024+256;
  float ir=gi[d], iz=gi[H2C+d], inn=gi[2*H2C+d];
  float hr=gh[d], hz=gh[H2C+d], hn=gh[2*H2C+d];
  float r=1.f/(1.f+expf(-(ir+hr)));
  float z=1.f/(1.f+expf(-(iz+hz)));
  float nn=tanhf(inn + r*hn);
  float hv=d_h[n*H2C+d];
  float nv=(1.f-z)*nn + z*hv;
  d_h[n*H2C+d]=nv;
  __nv_bfloat16 hi=__float2bfloat16(nv);
  d_hhi[n*H2C+d]=hi;
  d_hlo[n*H2C+d]=__float2bfloat16(nv-__bfloat162float(hi));
}

// ---------------- pooling (3 kernels) ----------------
__global__ void k_poolscore(const float* __restrict__ pW1,
                            const float* __restrict__ pb1,
                            const float* __restrict__ pv){
  int p=blockIdx.y, x8=blockIdx.x, j=threadIdx.x;
  __shared__ float xs[8][DHH];
  int coff=(p<2)? 0 : DHH;
  #pragma unroll
  for(int q=0;q<8;q++){
    int x=x8*8+q;
    if(x<NN+8){
      bool isB = x>=NN;
      int node = isB? (SPECIAL + x - NN) : x;
      const float* hb = isB? (d_h + (size_t)2048*H2C) : d_h;
      xs[q][j]=hb[(size_t)node*H2C+coff+j];
    } else xs[q][j]=0.f;
  }
  __syncthreads();
  const float* W = pW1 + p*DHH*DHH;
  float bb = pb1[p*DHH+j];
  float acc[8];
  #pragma unroll
  for(int q=0;q<8;q++) acc[q]=bb;
  for(int d=0;d<DHH;d++){
    float w = W[d*DHH+j];
    #pragma unroll
    for(int q=0;q<8;q++) acc[q]=fmaf(xs[q][d], w, acc[q]);
  }
  float pvj = pv[p*DHH+j];
  #pragma unroll
  for(int q=0;q<8;q++){
    float y = tanhf(acc[q])*pvj;
    float s = blkSum<128>(y);
    if(j==0){
      int x=x8*8+q;
      if(x<NN) d_tA[p*NN+x]=s;
      else if(x<NN+8) d_tB[p*8+(x-NN)]=s;
    }
  }
}

__global__ void k_poolpart(){
  int c=blockIdx.x, p=blockIdx.y, t=threadIdx.x;
  float mx=-1e30f;
  for(int n=t;n<NN;n+=128) mx=fmaxf(mx, d_tA[p*NN+n]);
  if(t<8) mx=fmaxf(mx, d_tB[p*8+t]);
  float M = blkMax<128>(mx);
  if(c==0 && t==0) d_Mx[p]=M;
  int n0=c*128;
  int lim = SPECIAL - n0; if(lim>128) lim=128; if(lim<0) lim=0;
  int coff=(p<2)? 0 : DHH;
  __shared__ float ws[128];
  float w = (t<lim)? expf(d_tA[p*NN+n0+t]-M) : 0.f;
  ws[t]=w;
  float den = blkSum<128>(w);
  float num=0.f;
  for(int i=0;i<lim;i++)
    num = fmaf(ws[i], d_h[(size_t)(n0+i)*H2C+coff+t], num);
  d_pNum[(p*16+c)*DHH+t]=num;
  if(t==0) d_pDen[p*16+c]=den;
}

__global__ void k_poolstates(){
  int s=blockIdx.x, p=blockIdx.y, d=threadIdx.x;
  int coff=(p<2)? 0 : DHH;
  float M=d_Mx[p];
  float num=0.f, den=0.f;
  #pragma unroll
  for(int c=0;c<16;c++){
    num += d_pNum[(p*16+c)*DHH+d];
    den += d_pDen[p*16+c];
  }
  #pragma unroll
  for(int j=0;j<8;j++){
    int node=SPECIAL+j;
    int bit=(s>>(7-j))&1;
    float tv = bit? d_tB[p*8+j] : d_tA[p*NN+node];
    float w = expf(tv-M);
    const float* h = bit? (d_h+(size_t)2048*H2C) : d_h;
    num = fmaf(w, h[(size_t)node*H2C+coff+d], num);
    den += w;
  }
  d_pooled[(p*SS+s)*DHH + d] = num/den;
}

// ---------------- outputs ----------------
__global__ void k_out(const float* __restrict__ finite,
                      const float* __restrict__ trans,
                      float* __restrict__ out){
  int a=blockIdx.x, b=threadIdx.x;
  int idx=a*256+b;
  out[idx]=d_ho[idx];
  out[65536+idx]= (finite[idx]>0.f)?1.f:0.f;
  out[3*65536+idx]=trans[idx];
  float x=d_ho[65536+idx];
  float M=blkMax<256>(x);
  float e=expf(x-M);
  float sum=blkSum<256>(e);
  out[2*65536 + idx] = x - M - logf(sum);
}

// ---------------- host ----------------
static float* symf(const void* s){ void* p=nullptr; cudaGetSymbolAddress(&p, s); return (float*)p; }
static __nv_bfloat16* symb(const void* s){ void* p=nullptr; cudaGetSymbolAddress(&p, s); return (__nv_bfloat16*)p; }

extern "C" void kernel_launch(void* const* d_in, const int* in_sizes, int n_in,
                              void* d_out, int out_size){
  const int*   edge_index=(const int*)d_in[0];
  const float* edge_attr =(const float*)d_in[1];
  const float* h_init0   =(const float*)d_in[2];
  const float* h_init1   =(const float*)d_in[3];
  const float* finite    =(const float*)d_in[4];
  const float* trans     =(const float*)d_in[5];
  const float* init_W    =(const float*)d_in[6];
  const float* init_b    =(const float*)d_in[7];
  const float* aggr_W    =(const float*)d_in[8];
  const float* aggr_b    =(const float*)d_in[9];
  const float* gWih      =(const float*)d_in[10];
  const float* gWhh      =(const float*)d_in[11];
  const float* gbih      =(const float*)d_in[12];
  const float* gbhh      =(const float*)d_in[13];
  const float* pW1       =(const float*)d_in[14];
  const float* pb1       =(const float*)d_in[15];
  const float* pv        =(const float*)d_in[16];
  const float* rW1       =(const float*)d_in[17];
  const float* rb1       =(const float*)d_in[18];
  const float* rg1       =(const float*)d_in[19];
  const float* rbe1      =(const float*)d_in[20];
  const float* rW2       =(const float*)d_in[21];
  const float* rb2       =(const float*)d_in[22];
  const float* rg2       =(const float*)d_in[23];
  const float* rbe2      =(const float*)d_in[24];
  const float* rW3       =(const float*)d_in[25];
  const float* rb3       =(const float*)d_in[26];
  const int* src=edge_index;
  const int* dst=edge_index+EE;
  float* out=(float*)d_out;

  float* P_bias1= symf(d_bias1);
  float* P_G1   = symf(d_G1);
  float* P_gi   = symf(d_gi);
  __nv_bfloat16* P_hhi  = symb(d_hhi);
  __nv_bfloat16* P_hlo  = symb(d_hlo);
  __nv_bfloat16* P_ahi  = symb(d_agghi);
  __nv_bfloat16* P_alo  = symb(d_agglo);
  __nv_bfloat16* P_B1h  = symb(d_B1t_hi);
  __nv_bfloat16* P_B1l  = symb(d_B1t_lo);
  __nv_bfloat16* P_B2h  = symb(d_B2t_hi);
  __nv_bfloat16* P_B2l  = symb(d_B2t_lo);

  cudaFuncSetAttribute(hmma, cudaFuncAttributeMaxDynamicSharedMemorySize, HSMEM);
  cudaFuncSetAttribute(k_ro, cudaFuncAttributeMaxDynamicSharedMemorySize, ROSMEM);

  // prep
  k_packAll<<<7762,256>>>(aggr_W, gWhh, gbhh, gWih, rW2);
  k_csr<<<1,1024>>>(src,dst);
  k_init<<<dim3(4,32,2),256>>>(h_init0, h_init1, init_W, init_b);

  // message passing (64x64 tiles: GEMM1 grid (16,64), GEMM2 grid (12,64))
  for(int r=0;r<4;r++){
    for(int p=0;p<2;p++){
      hmma<<<dim3(16,64),128,HSMEM>>>(2048,
        P_hhi, P_hlo,
        P_B1h+(size_t)p*262144, P_B1l+(size_t)p*262144,
        P_B1h+(size_t)(p+2)*262144, P_B1l+(size_t)(p+2)*262144,
        P_bias1+p*1024, P_bias1+(p+2)*1024, P_G1, 1024);
      k_gather<<<NB,256>>>(p, edge_attr, aggr_b);
      hmma<<<dim3(12,64),128,HSMEM>>>(2048,
        P_ahi, P_alo,
        P_B2h+(size_t)p*196608, P_B2l+(size_t)p*196608,
        P_B2h+(size_t)(p+2)*196608, P_B2l+(size_t)(p+2)*196608,
        gbih+p*G3C, gbih+(p+2)*G3C, P_gi, G3C);
      k_gru<<<NB,256>>>();
    }
  }

  // pooling (3 kernels)
  k_poolscore<<<dim3(257,4),128>>>(pW1,pb1,pv);
  k_poolpart<<<dim3(16,4),128>>>();
  k_poolstates<<<dim3(SS,4),128>>>();

  // readout
  k_qi<<<dim3(4,4,4),256>>>(rW1);
  k_ro<<<dim3(1024,2),256,ROSMEM>>>(rb1,rg1,rbe1,rb2,rg2,rbe2,rW3,rb3);

  // outputs
  k_out<<<SS,256>>>(finite,trans,out);
}